// round 6
// baseline (speedup 1.0000x reference)
#include <cuda_runtime.h>
#include <cstdint>

#define BATCH 16
#define SEQ   1024
#define CH    768
#define HEADS 12
#define DHEAD 64
#define NTOK  1220              // 1024 + 196
#define NKV   1280              // padded key count
#define MQKV  (BATCH*NTOK)      // 19520 rows of xt
#define MPAD  19584             // 153*128
#define QKVN  (3*CH)            // 2304
#define MOUT  (BATCH*SEQ)       // 16384

#if defined(__CUDA_ARCH_FEAT_SM103_ALL)
#define HAS_TC 1
#else
#define HAS_TC 0
#endif

// ---------------- scratch (zero-initialized at module load) ----------------
__device__ float g_XT [MPAD*CH];
__device__ float g_WT1[QKVN*CH];
__device__ float g_WT2[CH*CH];
__device__ float g_Q  [BATCH*HEADS*SEQ *DHEAD];
__device__ float g_K  [BATCH*HEADS*NKV *DHEAD];
__device__ float g_V  [BATCH*HEADS*NKV *DHEAD];
__device__ float g_AT [BATCH*SEQ*CH];
__device__ int   g_bad1;
__device__ int   g_bad2;
__device__ float g_sink;

// ---------------- helpers ----------------
__device__ __forceinline__ unsigned f2t(float x){
    unsigned u; asm("cvt.rna.tf32.f32 %0, %1;" : "=r"(u) : "f"(x)); return u;
}
__device__ __forceinline__ float tf32r(float x){
    unsigned u; asm("cvt.rna.tf32.f32 %0, %1;" : "=r"(u) : "f"(x));
    return __uint_as_float(u);
}
__device__ __forceinline__ void mma8(float* c, const unsigned* a, const unsigned* b){
    asm volatile("mma.sync.aligned.m16n8k8.row.col.f32.tf32.tf32.f32 "
        "{%0,%1,%2,%3}, {%4,%5,%6,%7}, {%8,%9}, {%0,%1,%2,%3};"
        : "+f"(c[0]), "+f"(c[1]), "+f"(c[2]), "+f"(c[3])
        : "r"(a[0]), "r"(a[1]), "r"(a[2]), "r"(a[3]), "r"(b[0]), "r"(b[1]));
}
__device__ __forceinline__ uint32_t smem_u32(const void* p){
    uint32_t a;
    asm("{ .reg .u64 t; cvta.to.shared.u64 t, %1; cvt.u32.u64 %0, t; }" : "=r"(a) : "l"(p));
    return a;
}
__device__ __forceinline__ uint32_t elect_one(){
    uint32_t p;
    asm volatile("{\n\t.reg .pred p;\n\telect.sync _|p, 0xFFFFFFFF;\n\t"
                 "selp.b32 %0, 1, 0, p;\n\t}" : "=r"(p));
    return p;
}
__device__ __forceinline__ void cpa16(uint32_t dst, const float* src){
    asm volatile("cp.async.cg.shared.global [%0], [%1], 16;" :: "r"(dst), "l"(src) : "memory");
}
__device__ __forceinline__ void cp_commit(){
    asm volatile("cp.async.commit_group;" ::: "memory");
}
__device__ __forceinline__ void mbar_init(uint32_t a, uint32_t cnt){
    asm volatile("mbarrier.init.shared.b64 [%0], %1;" :: "r"(a), "r"(cnt) : "memory");
}
__device__ __forceinline__ void mbar_wait(uint32_t a, uint32_t ph){
    asm volatile("{\n\t.reg .pred P;\n\tW%=:\n\t"
        "mbarrier.try_wait.parity.acquire.cta.shared::cta.b64 P, [%0], %1, 0x989680;\n\t"
        "@!P bra W%=;\n\t}" :: "r"(a), "r"(ph) : "memory");
}
#if HAS_TC
__device__ __forceinline__ void tc_commit(uint32_t mbar){
    asm volatile("tcgen05.commit.cta_group::1.mbarrier::arrive::one.shared::cluster.b64 [%0];"
                 :: "r"(mbar) : "memory");
}
__device__ __forceinline__ void mma_tf32(uint32_t d, uint64_t ad, uint64_t bd,
                                         uint32_t idesc, bool en){
    uint32_t e = en ? 1u : 0u;
    asm volatile("{\n\t.reg .pred p;\n\tsetp.ne.u32 p, %4, 0;\n\t"
        "tcgen05.mma.cta_group::1.kind::tf32 [%0], %1, %2, %3, {%5,%5,%5,%5}, p;\n\t}"
        :: "r"(d), "l"(ad), "l"(bd), "r"(idesc), "r"(e), "r"(0u) : "memory");
}
#endif
#define DESC_BASE ((2ull<<61)|(1ull<<46)|(64ull<<32)|(1ull<<16))
#define IDESC_TF32_N128 ((1u<<4)|(2u<<7)|(2u<<10)|((128u/8u)<<17)|((128u/16u)<<24))

// =====================================================================
// Prep A: materialize xt (tf32 rounded); thread 0 resets flags
// =====================================================================
__global__ __launch_bounds__(256) void xt_copy(
    const float* __restrict__ x, const float* __restrict__ sc)
{
    size_t i = (size_t)blockIdx.x * blockDim.x + threadIdx.x;
    if (i == 0) { g_bad1 = 0; g_bad2 = 0; }
    size_t tot = (size_t)MQKV * (CH/4);
    if (i >= tot) return;
    int row = (int)(i / (CH/4));
    int c4  = (int)(i % (CH/4)) * 4;
    int b = row / NTOK, t = row - b * NTOK;
    const float* src = (t < SEQ) ? (x + (size_t)(b * SEQ + t) * CH)
                                 : (sc + (size_t)(t - SEQ) * CH);
    float4 v = *(const float4*)(src + c4);
    *(float4*)(g_XT + (size_t)row * CH + c4) =
        make_float4(tf32r(v.x), tf32r(v.y), tf32r(v.z), tf32r(v.w));
}

// =====================================================================
// Prep B: transpose W[R,C] -> dst[C,R], tf32 rounded
// =====================================================================
__global__ void transpW(const float* __restrict__ src, float* __restrict__ dst,
                        int R, int C)
{
    __shared__ float tl[32][33];
    int c0 = blockIdx.x * 32, r0 = blockIdx.y * 32;
    for (int j = threadIdx.y; j < 32; j += 8) {
        int r = r0 + j, c = c0 + threadIdx.x;
        if (r < R && c < C) tl[j][threadIdx.x] = src[(size_t)r * C + c];
    }
    __syncthreads();
    for (int j = threadIdx.y; j < 32; j += 8) {
        int r = c0 + j, c = r0 + threadIdx.x;
        if (r < C && c < R) dst[(size_t)r * R + c] = tf32r(tl[threadIdx.x][j]);
    }
}

// =====================================================================
// tcgen05 SS tf32 GEMM, CTA tile 128x256, two N=128 MMAs per k-step.
// Writes its result into the REAL buffers; unconditional fallbacks
// overwrite afterward, so this is instrumentation-only this round.
// =====================================================================
#define GSTAGES 4
#define STAGE_BYTES 49152
#define GDSMEM (1024 + GSTAGES*STAGE_BYTES)

template<int MODE>
__global__ __launch_bounds__(256)
void gemm_tc(const float* __restrict__ A, const float* __restrict__ Bm,
             const float* __restrict__ bias, float* __restrict__ out)
{
#if HAS_TC
    constexpr int NKT = CH / 32;
    extern __shared__ char dsm[];
    __shared__ uint64_t s_mbar[GSTAGES];
    __shared__ uint32_t s_tmem;

    const uint32_t tile0 = (smem_u32(dsm) + 1023u) & ~1023u;
    const int tid = threadIdx.x, wid = tid >> 5, lane = tid & 31;
    const int mt = blockIdx.y, nt = blockIdx.x;

    if (tid == 0) {
        #pragma unroll
        for (int s = 0; s < GSTAGES; s++) mbar_init(smem_u32(&s_mbar[s]), 1);
    }
    if (wid == 0) {
        asm volatile("tcgen05.alloc.cta_group::1.sync.aligned.shared::cta.b32 [%0], %1;"
                     :: "r"(smem_u32(&s_tmem)), "r"(256u) : "memory");
        asm volatile("tcgen05.relinquish_alloc_permit.cta_group::1.sync.aligned;");
    }
    __syncthreads();
    const uint32_t tmem = s_tmem;

    const float* Arow = A  + (size_t)(mt * 128 + (tid >> 1)) * CH + (tid & 1) * 16;
    const float* Brow = Bm + (size_t)(nt * 256 + tid) * CH;
    const uint32_t a_off0 = (uint32_t)((tid >> 1) * 128 + (tid & 1) * 64);
    const uint32_t b_off0 = (uint32_t)(tid * 128);

    #pragma unroll
    for (int it = 0; it < GSTAGES - 1; it++) {
        uint32_t ab = tile0 + it * STAGE_BYTES, bb = ab + 16384;
        const float* As = Arow + it * 32;
        const float* Bs = Brow + it * 32;
        #pragma unroll
        for (int q = 0; q < 4; q++) {
            uint32_t o = a_off0 + q * 16;
            cpa16(ab + (o ^ ((o >> 3) & 0x70)), As + q * 4);
        }
        #pragma unroll
        for (int q = 0; q < 8; q++) {
            uint32_t o = b_off0 + q * 16;
            cpa16(bb + (o ^ ((o >> 3) & 0x70)), Bs + q * 4);
        }
        cp_commit();
    }

    for (int kt = 0; kt < NKT; kt++) {
        const int ld = kt + GSTAGES - 1;
        if (ld < NKT) {
            if (kt >= 1) {
                int j = kt - 1;
                mbar_wait(smem_u32(&s_mbar[j % GSTAGES]), (uint32_t)((j / GSTAGES) & 1));
            }
            uint32_t buf = ld % GSTAGES;
            uint32_t ab = tile0 + buf * STAGE_BYTES, bb = ab + 16384;
            const float* As = Arow + ld * 32;
            const float* Bs = Brow + ld * 32;
            #pragma unroll
            for (int q = 0; q < 4; q++) {
                uint32_t o = a_off0 + q * 16;
                cpa16(ab + (o ^ ((o >> 3) & 0x70)), As + q * 4);
            }
            #pragma unroll
            for (int q = 0; q < 8; q++) {
                uint32_t o = b_off0 + q * 16;
                cpa16(bb + (o ^ ((o >> 3) & 0x70)), Bs + q * 4);
            }
            cp_commit();
        } else {
            cp_commit();
        }
        asm volatile("cp.async.wait_group 3;" ::: "memory");
        __syncthreads();
        if (wid == 0 && elect_one()) {
            asm volatile("fence.proxy.async;" ::: "memory");
            asm volatile("tcgen05.fence::after_thread_sync;" ::: "memory");
            uint32_t buf = kt % GSTAGES;
            uint32_t ab = tile0 + buf * STAGE_BYTES, bb = ab + 16384;
            uint64_t ad  = DESC_BASE | (uint64_t)((ab >> 4) & 0x3FFF);
            uint64_t bd0 = DESC_BASE | (uint64_t)((bb >> 4) & 0x3FFF);
            uint64_t bd1 = bd0 + 1024;
            #pragma unroll
            for (int ks = 0; ks < 4; ks++) {
                bool en = (kt > 0) || (ks > 0);
                mma_tf32(tmem,       ad + ks * 2, bd0 + ks * 2, IDESC_TF32_N128, en);
                mma_tf32(tmem + 128, ad + ks * 2, bd1 + ks * 2, IDESC_TF32_N128, en);
            }
            tc_commit(smem_u32(&s_mbar[buf]));
        }
    }
    {
        int j = NKT - 1;
        mbar_wait(smem_u32(&s_mbar[j % GSTAGES]), (uint32_t)((j / GSTAGES) & 1));
    }
    asm volatile("tcgen05.fence::after_thread_sync;" ::: "memory");

    const int rrow = mt * 128 + (wid & 3) * 32 + lane;
    const int colb = nt * 256 + (wid >> 2) * 128;
    const uint32_t tm_base = tmem + ((uint32_t)(wid & 3) << 21) + (uint32_t)((wid >> 2) * 128);

    int b_ = 0, t_ = 0;
    if (MODE == 0 && rrow < MQKV) { b_ = rrow / NTOK; t_ = rrow - b_ * NTOK; }

    #pragma unroll
    for (int c0 = 0; c0 < 128; c0 += 32) {
        uint32_t r[32];
        asm volatile(
            "tcgen05.ld.sync.aligned.32x32b.x32.b32 "
            "{%0,%1,%2,%3,%4,%5,%6,%7,%8,%9,%10,%11,%12,%13,%14,%15,"
            "%16,%17,%18,%19,%20,%21,%22,%23,%24,%25,%26,%27,%28,%29,%30,%31}, [%32];"
            : "=r"(r[0]),"=r"(r[1]),"=r"(r[2]),"=r"(r[3]),"=r"(r[4]),"=r"(r[5]),
              "=r"(r[6]),"=r"(r[7]),"=r"(r[8]),"=r"(r[9]),"=r"(r[10]),"=r"(r[11]),
              "=r"(r[12]),"=r"(r[13]),"=r"(r[14]),"=r"(r[15]),"=r"(r[16]),"=r"(r[17]),
              "=r"(r[18]),"=r"(r[19]),"=r"(r[20]),"=r"(r[21]),"=r"(r[22]),"=r"(r[23]),
              "=r"(r[24]),"=r"(r[25]),"=r"(r[26]),"=r"(r[27]),"=r"(r[28]),"=r"(r[29]),
              "=r"(r[30]),"=r"(r[31])
            : "r"(tm_base + (uint32_t)c0));
        asm volatile("tcgen05.wait::ld.sync.aligned;" ::: "memory");
        if (MODE == 1) {
            #pragma unroll
            for (int i = 0; i < 32; i++) {
                int c = colb + c0 + i;
                out[(size_t)rrow * CH + c] = __uint_as_float(r[i]) + bias[c];
            }
        } else if (rrow < MQKV) {
            #pragma unroll
            for (int i = 0; i < 32; i++) {
                int c = colb + c0 + i;
                int wc = c / CH, cc = c - wc * CH;
                int h = cc >> 6, d = cc & 63;
                float v = __uint_as_float(r[i]);
                if (wc == 0) {
                    if (t_ < SEQ)
                        g_Q[((size_t)(b_ * HEADS + h) * SEQ + t_) * DHEAD + d] = v;
                } else if (wc == 1) {
                    g_K[((size_t)(b_ * HEADS + h) * NKV + t_) * DHEAD + d] = v;
                } else {
                    g_V[((size_t)(b_ * HEADS + h) * NKV + t_) * DHEAD + d] = v;
                }
            }
        }
    }
    __syncthreads();
    if (wid == 0) {
        asm volatile("tcgen05.dealloc.cta_group::1.sync.aligned.b32 %0, %1;"
                     :: "r"(tmem), "r"(256u));
    }
#endif
}

// =====================================================================
// Checks: 16 sampled rows per output column, scalar fp32 reference.
// =====================================================================
__global__ __launch_bounds__(256) void check_qkv()
{
    int c = blockIdx.x * 256 + threadIdx.x;
    if (c >= QKVN) return;
    const float* wcol = g_WT1 + (size_t)c * CH;
    int wc = c / CH, cc = c - wc * CH;
    int h = cc >> 6, d = cc & 63;
    bool bad = false;
    for (int s = 0; s < 16; s++) {
        int row = (c * 53 + s * 1217) % MQKV;
        int b = row / NTOK, t = row - b * NTOK;
        float acc = 0.f;
        const float* xr = g_XT + (size_t)row * CH;
        for (int k = 0; k < CH; k++) acc += xr[k] * wcol[k];
        float got;
        if (wc == 0) {
            if (t >= SEQ) continue;
            got = g_Q[((size_t)(b * HEADS + h) * SEQ + t) * DHEAD + d];
        } else if (wc == 1) {
            got = g_K[((size_t)(b * HEADS + h) * NKV + t) * DHEAD + d];
        } else {
            got = g_V[((size_t)(b * HEADS + h) * NKV + t) * DHEAD + d];
        }
        if (!(fabsf(got - acc) <= 5e-3f * fabsf(acc) + 5e-3f)) bad = true;  // catches NaN too
    }
    if (bad) atomicExch(&g_bad1, 1);
}

__global__ __launch_bounds__(256) void check_proj(
    const float* __restrict__ bias, const float* __restrict__ out)
{
    int c = blockIdx.x * 256 + threadIdx.x;
    if (c >= CH) return;
    const float* wcol = g_WT2 + (size_t)c * CH;
    bool bad = false;
    for (int s = 0; s < 16; s++) {
        int row = (c * 53 + s * 1031) % MOUT;
        float acc = 0.f;
        const float* ar = g_AT + (size_t)row * CH;
        for (int k = 0; k < CH; k++) acc += ar[k] * wcol[k];
        acc += bias[c];
        float got = out[(size_t)row * CH + c];
        if (!(fabsf(got - acc) <= 5e-3f * fabsf(acc) + 5e-3f)) bad = true;
    }
    if (bad) atomicExch(&g_bad2, 1);
}

// =====================================================================
// Diagnostic delay: encodes flag state into dur_us.
// g_bad1 -> ~+300us, g_bad2 -> ~+600us. Deterministic fixed trip counts.
// =====================================================================
__global__ void diag_delay()
{
    int n = 0;
    if (g_bad1) n += 135000;    // ~540K cyc ~ 300us
    if (g_bad2) n += 270000;    // ~1.08M cyc ~ 600us
    float x = 1.0000001f;
    #pragma unroll 1
    for (int i = 0; i < n; i++) x = fmaf(x, 1.0000001f, 1e-9f);
    if (x == 12345.678f) g_sink = x;   // never true; keeps the chain live
}

// =====================================================================
// UNCONDITIONAL fallbacks — the round-1 proven kernels. They always
// overwrite Q/K/V and out, guaranteeing round-1-quality output.
// =====================================================================
__global__ __launch_bounds__(256) void fb_qkv(
    const float* __restrict__ x, const float* __restrict__ sc,
    const float* __restrict__ W)
{
    __shared__ unsigned As[128][36];
    __shared__ unsigned Bs[32][132];

    const int mt = blockIdx.y, nt = blockIdx.x;
    const int tid = threadIdx.x;
    const int wid = tid >> 5, lane = tid & 31;
    const int g = lane >> 2, tg = lane & 3;
    const int wm = (wid & 3) * 32, wn = (wid >> 2) * 64;

    float Creg[2][8][4];
    #pragma unroll
    for (int i = 0; i < 2; i++)
        #pragma unroll
        for (int j = 0; j < 8; j++)
            #pragma unroll
            for (int e = 0; e < 4; e++) Creg[i][j][e] = 0.f;

    for (int kt = 0; kt < CH / 32; kt++) {
        const int kt0 = kt * 32;
        #pragma unroll
        for (int i = 0; i < 4; i++) {
            int slot = tid + i * 256;
            int row = slot >> 3, kc = (slot & 7) * 4;
            int gr = mt * 128 + row;
            float4 v = make_float4(0.f, 0.f, 0.f, 0.f);
            if (gr < MQKV) {
                int b = gr / NTOK, t = gr - b * NTOK;
                const float* src = (t < SEQ) ? (x + (size_t)(b * SEQ + t) * CH)
                                             : (sc + (size_t)(t - SEQ) * CH);
                v = *(const float4*)(src + kt0 + kc);
            }
            *(uint4*)&As[row][kc] = make_uint4(f2t(v.x), f2t(v.y), f2t(v.z), f2t(v.w));
        }
        #pragma unroll
        for (int i = 0; i < 4; i++) {
            int slot = tid + i * 256;
            int kr = slot >> 5, nc = (slot & 31) * 4;
            float4 v = *(const float4*)(W + (size_t)(kt0 + kr) * QKVN + nt * 128 + nc);
            *(uint4*)&Bs[kr][nc] = make_uint4(f2t(v.x), f2t(v.y), f2t(v.z), f2t(v.w));
        }
        __syncthreads();
        #pragma unroll
        for (int ks = 0; ks < 4; ks++) {
            const int kk = ks * 8;
            unsigned a[2][4];
            #pragma unroll
            for (int mf = 0; mf < 2; mf++) {
                int r0 = wm + mf * 16 + g;
                a[mf][0] = As[r0    ][kk + tg];
                a[mf][1] = As[r0 + 8][kk + tg];
                a[mf][2] = As[r0    ][kk + tg + 4];
                a[mf][3] = As[r0 + 8][kk + tg + 4];
            }
            unsigned bf[8][2];
            #pragma unroll
            for (int nf = 0; nf < 8; nf++) {
                int c0 = wn + nf * 8 + g;
                bf[nf][0] = Bs[kk + tg    ][c0];
                bf[nf][1] = Bs[kk + tg + 4][c0];
            }
            #pragma unroll
            for (int mf = 0; mf < 2; mf++)
                #pragma unroll
                for (int nf = 0; nf < 8; nf++)
                    mma8(Creg[mf][nf], a[mf], bf[nf]);
        }
        __syncthreads();
    }
    #pragma unroll
    for (int mf = 0; mf < 2; mf++) {
        #pragma unroll
        for (int nf = 0; nf < 8; nf++) {
            #pragma unroll
            for (int e = 0; e < 4; e++) {
                int r = mt * 128 + wm + mf * 16 + g + ((e >= 2) ? 8 : 0);
                int c = nt * 128 + wn + nf * 8 + tg * 2 + (e & 1);
                if (r >= MQKV) continue;
                int b = r / NTOK, t = r - b * NTOK;
                int wc = c / CH, cc = c - wc * CH;
                int h = cc >> 6, d = cc & 63;
                float v = Creg[mf][nf][e];
                if (wc == 0) {
                    if (t < SEQ) g_Q[((size_t)(b * HEADS + h) * SEQ + t) * DHEAD + d] = v;
                } else if (wc == 1) {
                    g_K[((size_t)(b * HEADS + h) * NKV + t) * DHEAD + d] = v;
                } else {
                    g_V[((size_t)(b * HEADS + h) * NKV + t) * DHEAD + d] = v;
                }
            }
        }
    }
}

__global__ __launch_bounds__(256) void fb_proj(
    const float* __restrict__ W, const float* __restrict__ bias,
    float* __restrict__ out)
{
    __shared__ unsigned As[128][36];
    __shared__ unsigned Bs[32][132];

    const int mt = blockIdx.y, nt = blockIdx.x;
    const int tid = threadIdx.x;
    const int wid = tid >> 5, lane = tid & 31;
    const int g = lane >> 2, tg = lane & 3;
    const int wm = (wid & 3) * 32, wn = (wid >> 2) * 64;

    float Creg[2][8][4];
    #pragma unroll
    for (int i = 0; i < 2; i++)
        #pragma unroll
        for (int j = 0; j < 8; j++)
            #pragma unroll
            for (int e = 0; e < 4; e++) Creg[i][j][e] = 0.f;

    for (int kt = 0; kt < CH / 32; kt++) {
        const int kt0 = kt * 32;
        #pragma unroll
        for (int i = 0; i < 4; i++) {
            int slot = tid + i * 256;
            int row = slot >> 3, kc = (slot & 7) * 4;
            float4 v = *(const float4*)(g_AT + (size_t)(mt * 128 + row) * CH + kt0 + kc);
            *(uint4*)&As[row][kc] = make_uint4(f2t(v.x), f2t(v.y), f2t(v.z), f2t(v.w));
        }
        #pragma unroll
        for (int i = 0; i < 4; i++) {
            int slot = tid + i * 256;
            int kr = slot >> 5, nc = (slot & 31) * 4;
            float4 v = *(const float4*)(W + (size_t)(kt0 + kr) * CH + nt * 128 + nc);
            *(uint4*)&Bs[kr][nc] = make_uint4(f2t(v.x), f2t(v.y), f2t(v.z), f2t(v.w));
        }
        __syncthreads();
        #pragma unroll
        for (int ks = 0; ks < 4; ks++) {
            const int kk = ks * 8;
            unsigned a[2][4];
            #pragma unroll
            for (int mf = 0; mf < 2; mf++) {
                int r0 = wm + mf * 16 + g;
                a[mf][0] = As[r0    ][kk + tg];
                a[mf][1] = As[r0 + 8][kk + tg];
                a[mf][2] = As[r0    ][kk + tg + 4];
                a[mf][3] = As[r0 + 8][kk + tg + 4];
            }
            unsigned bf[8][2];
            #pragma unroll
            for (int nf = 0; nf < 8; nf++) {
                int c0 = wn + nf * 8 + g;
                bf[nf][0] = Bs[kk + tg    ][c0];
                bf[nf][1] = Bs[kk + tg + 4][c0];
            }
            #pragma unroll
            for (int mf = 0; mf < 2; mf++)
                #pragma unroll
                for (int nf = 0; nf < 8; nf++)
                    mma8(Creg[mf][nf], a[mf], bf[nf]);
        }
        __syncthreads();
    }
    #pragma unroll
    for (int mf = 0; mf < 2; mf++) {
        #pragma unroll
        for (int nf = 0; nf < 8; nf++) {
            int r = mt * 128 + wm + mf * 16 + g;
            int c = nt * 128 + wn + nf * 8 + tg * 2;
            float b0 = bias[c], b1 = bias[c + 1];
            out[(size_t)r * CH + c    ] = Creg[mf][nf][0] + b0;
            out[(size_t)r * CH + c + 1] = Creg[mf][nf][1] + b1;
            out[(size_t)(r + 8) * CH + c    ] = Creg[mf][nf][2] + b0;
            out[(size_t)(r + 8) * CH + c + 1] = Creg[mf][nf][3] + b1;
        }
    }
}

// =====================================================================
// Flash attention (proven round-1 kernel, unchanged).
// =====================================================================
__global__ __launch_bounds__(128) void attn_kernel()
{
    __shared__ unsigned Ks[64][72];
    __shared__ unsigned Vs[64][72];

    const int bh = blockIdx.y, qt = blockIdx.x;
    const int b = bh / HEADS, h = bh - b * HEADS;
    const int tid = threadIdx.x;
    const int w = tid >> 5, lane = tid & 31;
    const int g = lane >> 2, tg = lane & 3;

    const float* Qp = g_Q + (size_t)bh * SEQ * DHEAD;
    const float* Kp = g_K + (size_t)bh * NKV * DHEAD;
    const float* Vp = g_V + (size_t)bh * NKV * DHEAD;
    const int q0 = qt * 64 + w * 16;

    unsigned aq[8][4];
    #pragma unroll
    for (int ks = 0; ks < 8; ks++) {
        aq[ks][0] = f2t(Qp[(size_t)(q0 + g    ) * DHEAD + ks * 8 + tg    ]);
        aq[ks][1] = f2t(Qp[(size_t)(q0 + g + 8) * DHEAD + ks * 8 + tg    ]);
        aq[ks][2] = f2t(Qp[(size_t)(q0 + g    ) * DHEAD + ks * 8 + tg + 4]);
        aq[ks][3] = f2t(Qp[(size_t)(q0 + g + 8) * DHEAD + ks * 8 + tg + 4]);
    }

    float O[8][4];
    #pragma unroll
    for (int i = 0; i < 8; i++)
        #pragma unroll
        for (int e = 0; e < 4; e++) O[i][e] = 0.f;
    float mrow[2] = { -1e30f, -1e30f };
    float lrow[2] = { 0.f, 0.f };

    for (int kt = 0; kt < NKV / 64; kt++) {
        const int j0 = kt * 64;
        #pragma unroll
        for (int i = 0; i < 8; i++) {
            int slot = tid + i * 128;
            int row = slot >> 4, c4 = (slot & 15) * 4;
            float4 kv = *(const float4*)(Kp + (size_t)(j0 + row) * DHEAD + c4);
            *(uint4*)&Ks[row][c4] = make_uint4(f2t(kv.x), f2t(kv.y), f2t(kv.z), f2t(kv.w));
            float4 vv = *(const float4*)(Vp + (size_t)(j0 + row) * DHEAD + c4);
            *(uint4*)&Vs[row][c4] = make_uint4(f2t(vv.x), f2t(vv.y), f2t(vv.z), f2t(vv.w));
        }
        __syncthreads();

        float S[8][4];
        #pragma unroll
        for (int i = 0; i < 8; i++)
            #pragma unroll
            for (int e = 0; e < 4; e++) S[i][e] = 0.f;
        #pragma unroll
        for (int nf = 0; nf < 8; nf++) {
            #pragma unroll
            for (int ks = 0; ks < 8; ks++) {
                unsigned bb[2];
                bb[0] = Ks[nf * 8 + g][ks * 8 + tg    ];
                bb[1] = Ks[nf * 8 + g][ks * 8 + tg + 4];
                mma8(S[nf], aq[ks], bb);
            }
        }
        __syncthreads();

        #pragma unroll
        for (int nf = 0; nf < 8; nf++) {
            #pragma unroll
            for (int e = 0; e < 4; e++) {
                float s = S[nf][e] * 0.125f;
                int j = j0 + nf * 8 + tg * 2 + (e & 1);
                if (j >= NTOK) s = -1e30f;
                S[nf][e] = s;
            }
        }
        #pragma unroll
        for (int r = 0; r < 2; r++) {
            float mx = -1e30f;
            #pragma unroll
            for (int nf = 0; nf < 8; nf++) {
                mx = fmaxf(mx, S[nf][2 * r]);
                mx = fmaxf(mx, S[nf][2 * r + 1]);
            }
            mx = fmaxf(mx, __shfl_xor_sync(0xffffffffu, mx, 1));
            mx = fmaxf(mx, __shfl_xor_sync(0xffffffffu, mx, 2));
            float mnew = fmaxf(mrow[r], mx);
            float alpha = __expf(mrow[r] - mnew);
            float sum = 0.f;
            #pragma unroll
            for (int nf = 0; nf < 8; nf++) {
                float p0 = __expf(S[nf][2 * r    ] - mnew);
                float p1 = __expf(S[nf][2 * r + 1] - mnew);
                S[nf][2 * r] = p0; S[nf][2 * r + 1] = p1;
                sum += p0 + p1;
            }
            sum += __shfl_xor_sync(0xffffffffu, sum, 1);
            sum += __shfl_xor_sync(0xffffffffu, sum, 2);
            lrow[r] = lrow[r] * alpha + sum;
            mrow[r] = mnew;
            #pragma unroll
            for (int nf = 0; nf < 8; nf++) {
                O[nf][2 * r] *= alpha; O[nf][2 * r + 1] *= alpha;
            }
        }
        #pragma unroll
        for (int nf = 0; nf < 8; nf++) {
            Ks[w * 16 + g    ][nf * 8 + tg * 2    ] = f2t(S[nf][0]);
            Ks[w * 16 + g    ][nf * 8 + tg * 2 + 1] = f2t(S[nf][1]);
            Ks[w * 16 + g + 8][nf * 8 + tg * 2    ] = f2t(S[nf][2]);
            Ks[w * 16 + g + 8][nf * 8 + tg * 2 + 1] = f2t(S[nf][3]);
        }
        __syncwarp();
        #pragma unroll
        for (int ks = 0; ks < 8; ks++) {
            unsigned ap[4];
            ap[0] = Ks[w * 16 + g    ][ks * 8 + tg    ];
            ap[1] = Ks[w * 16 + g + 8][ks * 8 + tg    ];
            ap[2] = Ks[w * 16 + g    ][ks * 8 + tg + 4];
            ap[3] = Ks[w * 16 + g + 8][ks * 8 + tg + 4];
            #pragma unroll
            for (int nf = 0; nf < 8; nf++) {
                unsigned bb[2];
                bb[0] = Vs[ks * 8 + tg    ][nf * 8 + g];
                bb[1] = Vs[ks * 8 + tg + 4][nf * 8 + g];
                mma8(O[nf], ap, bb);
            }
        }
        __syncthreads();
    }
    float inv0 = 1.f / lrow[0], inv1 = 1.f / lrow[1];
    int row0 = b * SEQ + qt * 64 + w * 16 + g;
    #pragma unroll
    for (int nf = 0; nf < 8; nf++) {
        int col = h * DHEAD + nf * 8 + tg * 2;
        g_AT[(size_t)row0 * CH + col    ] = O[nf][0] * inv0;
        g_AT[(size_t)row0 * CH + col + 1] = O[nf][1] * inv0;
        g_AT[(size_t)(row0 + 8) * CH + col    ] = O[nf][2] * inv1;
        g_AT[(size_t)(row0 + 8) * CH + col + 1] = O[nf][3] * inv1;
    }
}

// =====================================================================
extern "C" void kernel_launch(void* const* d_in, const int* in_sizes, int n_in,
                              void* d_out, int out_size)
{
    const float* x     = (const float*)d_in[0];
    const float* sc    = (const float*)d_in[1];
    const float* Wqkv  = (const float*)d_in[2];
    const float* Wproj = (const float*)d_in[3];
    const float* bproj = (const float*)d_in[4];
    float* out = (float*)d_out;

    cudaFuncSetAttribute(gemm_tc<0>, cudaFuncAttributeMaxDynamicSharedMemorySize, GDSMEM);
    cudaFuncSetAttribute(gemm_tc<1>, cudaFuncAttributeMaxDynamicSharedMemorySize, GDSMEM);

    {
        size_t tot = (size_t)MQKV * (CH / 4);
        xt_copy<<<(unsigned)((tot + 255) / 256), 256>>>(x, sc);
    }
    transpW<<<dim3(QKVN / 32, CH / 32), dim3(32, 8)>>>(Wqkv, g_WT1, CH, QKVN);
    transpW<<<dim3(CH / 32, CH / 32), dim3(32, 8)>>>(Wproj, g_WT2, CH, CH);

    // tc qkv (instrumented) -> check -> unconditional proven overwrite
    gemm_tc<0><<<dim3(9, 153), 256, GDSMEM>>>(g_XT, g_WT1, nullptr, nullptr);
    check_qkv<<<9, 256>>>();
    fb_qkv<<<dim3(18, 153), 256>>>(x, sc, Wqkv);

    attn_kernel<<<dim3(16, 192), 128>>>();

    // tc proj (instrumented) -> check -> unconditional proven overwrite
    gemm_tc<1><<<dim3(3, 128), 256, GDSMEM>>>(g_AT, g_WT2, bproj, out);
    check_proj<<<3, 256>>>(bproj, out);
    fb_proj<<<dim3(6, 128), 256>>>(Wproj, bproj, out);

    // encode check outcomes into dur_us: +~300us if qkv-tc bad, +~600us if proj-tc bad
    diag_delay<<<1, 1>>>();
}

// round 8
// speedup vs baseline: 25.4331x; 25.4331x over previous
#include <cuda_runtime.h>
#include <cstdint>

#define BATCH 16
#define SEQ   1024
#define CH    768
#define HEADS 12
#define DHEAD 64
#define NTOK  1220              // 1024 + 196
#define NKV   1280              // padded key count
#define MQKV  (BATCH*NTOK)      // 19520 rows of xt
#define QKVN  (3*CH)            // 2304

// ---------------- scratch (zero-initialized at module load; pad rows of K/V
// are never written so they stay 0.0 deterministically) ----------------------
__device__ float g_Q [BATCH*HEADS*SEQ *DHEAD];   // [b][h][t<1024][d]
__device__ float g_K [BATCH*HEADS*NKV *DHEAD];   // [b][h][t<1280][d]
__device__ float g_V [BATCH*HEADS*NKV *DHEAD];
__device__ float g_AT[BATCH*SEQ*CH];             // attention out [b*1024+t][h*64+d]

// ---------------- tf32 helpers ----------------
__device__ __forceinline__ unsigned f2t(float x){
    unsigned u; asm("cvt.rna.tf32.f32 %0, %1;" : "=r"(u) : "f"(x)); return u;
}
__device__ __forceinline__ void mma8(float* c, const unsigned* a, const unsigned* b){
    asm volatile("mma.sync.aligned.m16n8k8.row.col.f32.tf32.tf32.f32 "
        "{%0,%1,%2,%3}, {%4,%5,%6,%7}, {%8,%9}, {%0,%1,%2,%3};"
        : "+f"(c[0]), "+f"(c[1]), "+f"(c[2]), "+f"(c[3])
        : "r"(a[0]), "r"(a[1]), "r"(a[2]), "r"(a[3]), "r"(b[0]), "r"(b[1]));
}

// =====================================================================
// Kernel 1: QKV GEMM.  xt[19520,768] @ W_qkv[768,2304] -> g_Q/g_K/g_V.
// Block tile 128x128, k-tile 32. CHANGE vs round 1: 4 warps with 64x64
// warp tiles (was 8 warps of 32x64) -> A-fragment LDS traffic halved.
// Staging identical to round 1: LDG -> cvt -> STS, same strides.
// =====================================================================
__global__ __launch_bounds__(128) void qkv_gemm(
    const float* __restrict__ x, const float* __restrict__ sc,
    const float* __restrict__ W)
{
    __shared__ unsigned As[128][36];   // [m][k]
    __shared__ unsigned Bs[32][132];   // [k][n]

    const int mt = blockIdx.y, nt = blockIdx.x;
    const int tid = threadIdx.x;
    const int wid = tid >> 5, lane = tid & 31;
    const int g = lane >> 2, tg = lane & 3;
    const int wm = (wid & 1) * 64, wn = (wid >> 1) * 64;

    float Creg[4][8][4];
    #pragma unroll
    for (int i = 0; i < 4; i++)
        #pragma unroll
        for (int j = 0; j < 8; j++)
            #pragma unroll
            for (int e = 0; e < 4; e++) Creg[i][j][e] = 0.f;

    for (int kt = 0; kt < CH / 32; kt++) {
        const int kt0 = kt * 32;
        // ---- load A tile (xt row mapping), 128 threads x 8 iters ----
        #pragma unroll
        for (int i = 0; i < 8; i++) {
            int slot = tid + i * 128;
            int row = slot >> 3, kc = (slot & 7) * 4;
            int gr = mt * 128 + row;
            float4 v = make_float4(0.f, 0.f, 0.f, 0.f);
            if (gr < MQKV) {
                int b = gr / NTOK, t = gr - b * NTOK;
                const float* src = (t < SEQ) ? (x + (size_t)(b * SEQ + t) * CH)
                                             : (sc + (size_t)(t - SEQ) * CH);
                v = *(const float4*)(src + kt0 + kc);
            }
            *(uint4*)&As[row][kc] = make_uint4(f2t(v.x), f2t(v.y), f2t(v.z), f2t(v.w));
        }
        // ---- load B tile ----
        #pragma unroll
        for (int i = 0; i < 8; i++) {
            int slot = tid + i * 128;
            int kr = slot >> 5, nc = (slot & 31) * 4;
            float4 v = *(const float4*)(W + (size_t)(kt0 + kr) * QKVN + nt * 128 + nc);
            *(uint4*)&Bs[kr][nc] = make_uint4(f2t(v.x), f2t(v.y), f2t(v.z), f2t(v.w));
        }
        __syncthreads();
        // ---- compute: 4 ks x (4 mf x 8 nf) ----
        #pragma unroll
        for (int ks = 0; ks < 4; ks++) {
            const int kk = ks * 8;
            unsigned a[4][4];
            #pragma unroll
            for (int mf = 0; mf < 4; mf++) {
                int r0 = wm + mf * 16 + g;
                a[mf][0] = As[r0    ][kk + tg];
                a[mf][1] = As[r0 + 8][kk + tg];
                a[mf][2] = As[r0    ][kk + tg + 4];
                a[mf][3] = As[r0 + 8][kk + tg + 4];
            }
            unsigned bf[8][2];
            #pragma unroll
            for (int nf = 0; nf < 8; nf++) {
                int c0 = wn + nf * 8 + g;
                bf[nf][0] = Bs[kk + tg    ][c0];
                bf[nf][1] = Bs[kk + tg + 4][c0];
            }
            #pragma unroll
            for (int mf = 0; mf < 4; mf++)
                #pragma unroll
                for (int nf = 0; nf < 8; nf++)
                    mma8(Creg[mf][nf], a[mf], bf[nf]);
        }
        __syncthreads();
    }
    // ---- epilogue: scatter into Q/K/V (identical mapping to round 1) ----
    #pragma unroll
    for (int mf = 0; mf < 4; mf++) {
        #pragma unroll
        for (int nf = 0; nf < 8; nf++) {
            #pragma unroll
            for (int e = 0; e < 4; e++) {
                int r = mt * 128 + wm + mf * 16 + g + ((e >= 2) ? 8 : 0);
                int c = nt * 128 + wn + nf * 8 + tg * 2 + (e & 1);
                if (r >= MQKV) continue;
                int b = r / NTOK, t = r - b * NTOK;
                int which = c / CH, cc = c - which * CH;
                int h = cc >> 6, d = cc & 63;
                float v = Creg[mf][nf][e];
                if (which == 0) {
                    if (t < SEQ) g_Q[((size_t)(b * HEADS + h) * SEQ + t) * DHEAD + d] = v;
                } else if (which == 1) {
                    g_K[((size_t)(b * HEADS + h) * NKV + t) * DHEAD + d] = v;
                } else {
                    g_V[((size_t)(b * HEADS + h) * NKV + t) * DHEAD + d] = v;
                }
            }
        }
    }
}

// =====================================================================
// Kernel 2: flash attention — BYTE-IDENTICAL to the proven round-1
// kernel. grid = (16 q-tiles, 192 bh), 4 warps, 64 q rows/block.
// =====================================================================
__global__ __launch_bounds__(128) void attn_kernel()
{
    __shared__ unsigned Ks[64][72];   // K tile, then reused for P
    __shared__ unsigned Vs[64][72];

    const int bh = blockIdx.y, qt = blockIdx.x;
    const int b = bh / HEADS, h = bh - b * HEADS;
    const int tid = threadIdx.x;
    const int w = tid >> 5, lane = tid & 31;
    const int g = lane >> 2, tg = lane & 3;

    const float* Qp = g_Q + (size_t)bh * SEQ * DHEAD;
    const float* Kp = g_K + (size_t)bh * NKV * DHEAD;
    const float* Vp = g_V + (size_t)bh * NKV * DHEAD;
    const int q0 = qt * 64 + w * 16;

    unsigned aq[8][4];
    #pragma unroll
    for (int ks = 0; ks < 8; ks++) {
        aq[ks][0] = f2t(Qp[(size_t)(q0 + g    ) * DHEAD + ks * 8 + tg    ]);
        aq[ks][1] = f2t(Qp[(size_t)(q0 + g + 8) * DHEAD + ks * 8 + tg    ]);
        aq[ks][2] = f2t(Qp[(size_t)(q0 + g    ) * DHEAD + ks * 8 + tg + 4]);
        aq[ks][3] = f2t(Qp[(size_t)(q0 + g + 8) * DHEAD + ks * 8 + tg + 4]);
    }

    float O[8][4];
    #pragma unroll
    for (int i = 0; i < 8; i++)
        #pragma unroll
        for (int e = 0; e < 4; e++) O[i][e] = 0.f;
    float mrow[2] = { -1e30f, -1e30f };
    float lrow[2] = { 0.f, 0.f };

    for (int kt = 0; kt < NKV / 64; kt++) {
        const int j0 = kt * 64;
        #pragma unroll
        for (int i = 0; i < 8; i++) {
            int slot = tid + i * 128;
            int row = slot >> 4, c4 = (slot & 15) * 4;
            float4 kv = *(const float4*)(Kp + (size_t)(j0 + row) * DHEAD + c4);
            *(uint4*)&Ks[row][c4] = make_uint4(f2t(kv.x), f2t(kv.y), f2t(kv.z), f2t(kv.w));
            float4 vv = *(const float4*)(Vp + (size_t)(j0 + row) * DHEAD + c4);
            *(uint4*)&Vs[row][c4] = make_uint4(f2t(vv.x), f2t(vv.y), f2t(vv.z), f2t(vv.w));
        }
        __syncthreads();

        float S[8][4];
        #pragma unroll
        for (int i = 0; i < 8; i++)
            #pragma unroll
            for (int e = 0; e < 4; e++) S[i][e] = 0.f;
        #pragma unroll
        for (int nf = 0; nf < 8; nf++) {
            #pragma unroll
            for (int ks = 0; ks < 8; ks++) {
                unsigned bb[2];
                bb[0] = Ks[nf * 8 + g][ks * 8 + tg    ];
                bb[1] = Ks[nf * 8 + g][ks * 8 + tg + 4];
                mma8(S[nf], aq[ks], bb);
            }
        }
        __syncthreads();   // everyone done reading Ks before it becomes P

        #pragma unroll
        for (int nf = 0; nf < 8; nf++) {
            #pragma unroll
            for (int e = 0; e < 4; e++) {
                float s = S[nf][e] * 0.125f;
                int j = j0 + nf * 8 + tg * 2 + (e & 1);
                if (j >= NTOK) s = -1e30f;
                S[nf][e] = s;
            }
        }
        #pragma unroll
        for (int r = 0; r < 2; r++) {
            float mx = -1e30f;
            #pragma unroll
            for (int nf = 0; nf < 8; nf++) {
                mx = fmaxf(mx, S[nf][2 * r]);
                mx = fmaxf(mx, S[nf][2 * r + 1]);
            }
            mx = fmaxf(mx, __shfl_xor_sync(0xffffffffu, mx, 1));
            mx = fmaxf(mx, __shfl_xor_sync(0xffffffffu, mx, 2));
            float mnew = fmaxf(mrow[r], mx);
            float alpha = __expf(mrow[r] - mnew);
            float sum = 0.f;
            #pragma unroll
            for (int nf = 0; nf < 8; nf++) {
                float p0 = __expf(S[nf][2 * r    ] - mnew);
                float p1 = __expf(S[nf][2 * r + 1] - mnew);
                S[nf][2 * r] = p0; S[nf][2 * r + 1] = p1;
                sum += p0 + p1;
            }
            sum += __shfl_xor_sync(0xffffffffu, sum, 1);
            sum += __shfl_xor_sync(0xffffffffu, sum, 2);
            lrow[r] = lrow[r] * alpha + sum;
            mrow[r] = mnew;
            #pragma unroll
            for (int nf = 0; nf < 8; nf++) {
                O[nf][2 * r] *= alpha; O[nf][2 * r + 1] *= alpha;
            }
        }
        #pragma unroll
        for (int nf = 0; nf < 8; nf++) {
            Ks[w * 16 + g    ][nf * 8 + tg * 2    ] = f2t(S[nf][0]);
            Ks[w * 16 + g    ][nf * 8 + tg * 2 + 1] = f2t(S[nf][1]);
            Ks[w * 16 + g + 8][nf * 8 + tg * 2    ] = f2t(S[nf][2]);
            Ks[w * 16 + g + 8][nf * 8 + tg * 2 + 1] = f2t(S[nf][3]);
        }
        __syncwarp();
        #pragma unroll
        for (int ks = 0; ks < 8; ks++) {
            unsigned ap[4];
            ap[0] = Ks[w * 16 + g    ][ks * 8 + tg    ];
            ap[1] = Ks[w * 16 + g + 8][ks * 8 + tg    ];
            ap[2] = Ks[w * 16 + g    ][ks * 8 + tg + 4];
            ap[3] = Ks[w * 16 + g + 8][ks * 8 + tg + 4];
            #pragma unroll
            for (int nf = 0; nf < 8; nf++) {
                unsigned bb[2];
                bb[0] = Vs[ks * 8 + tg    ][nf * 8 + g];
                bb[1] = Vs[ks * 8 + tg + 4][nf * 8 + g];
                mma8(O[nf], ap, bb);
            }
        }
        __syncthreads();
    }
    float inv0 = 1.f / lrow[0], inv1 = 1.f / lrow[1];
    int row0 = b * SEQ + qt * 64 + w * 16 + g;
    #pragma unroll
    for (int nf = 0; nf < 8; nf++) {
        int col = h * DHEAD + nf * 8 + tg * 2;
        g_AT[(size_t)row0 * CH + col    ] = O[nf][0] * inv0;
        g_AT[(size_t)row0 * CH + col + 1] = O[nf][1] * inv0;
        g_AT[(size_t)(row0 + 8) * CH + col    ] = O[nf][2] * inv1;
        g_AT[(size_t)(row0 + 8) * CH + col + 1] = O[nf][3] * inv1;
    }
}

// =====================================================================
// Kernel 3: proj GEMM + bias, same 64x64-warp-tile upgrade.
// =====================================================================
__global__ __launch_bounds__(128) void proj_gemm(
    const float* __restrict__ W, const float* __restrict__ bias,
    float* __restrict__ out)
{
    __shared__ unsigned As[128][36];
    __shared__ unsigned Bs[32][132];

    const int mt = blockIdx.y, nt = blockIdx.x;
    const int tid = threadIdx.x;
    const int wid = tid >> 5, lane = tid & 31;
    const int g = lane >> 2, tg = lane & 3;
    const int wm = (wid & 1) * 64, wn = (wid >> 1) * 64;

    float Creg[4][8][4];
    #pragma unroll
    for (int i = 0; i < 4; i++)
        #pragma unroll
        for (int j = 0; j < 8; j++)
            #pragma unroll
            for (int e = 0; e < 4; e++) Creg[i][j][e] = 0.f;

    for (int kt = 0; kt < CH / 32; kt++) {
        const int kt0 = kt * 32;
        #pragma unroll
        for (int i = 0; i < 8; i++) {
            int slot = tid + i * 128;
            int row = slot >> 3, kc = (slot & 7) * 4;
            float4 v = *(const float4*)(g_AT + (size_t)(mt * 128 + row) * CH + kt0 + kc);
            *(uint4*)&As[row][kc] = make_uint4(f2t(v.x), f2t(v.y), f2t(v.z), f2t(v.w));
        }
        #pragma unroll
        for (int i = 0; i < 8; i++) {
            int slot = tid + i * 128;
            int kr = slot >> 5, nc = (slot & 31) * 4;
            float4 v = *(const float4*)(W + (size_t)(kt0 + kr) * CH + nt * 128 + nc);
            *(uint4*)&Bs[kr][nc] = make_uint4(f2t(v.x), f2t(v.y), f2t(v.z), f2t(v.w));
        }
        __syncthreads();
        #pragma unroll
        for (int ks = 0; ks < 4; ks++) {
            const int kk = ks * 8;
            unsigned a[4][4];
            #pragma unroll
            for (int mf = 0; mf < 4; mf++) {
                int r0 = wm + mf * 16 + g;
                a[mf][0] = As[r0    ][kk + tg];
                a[mf][1] = As[r0 + 8][kk + tg];
                a[mf][2] = As[r0    ][kk + tg + 4];
                a[mf][3] = As[r0 + 8][kk + tg + 4];
            }
            unsigned bf[8][2];
            #pragma unroll
            for (int nf = 0; nf < 8; nf++) {
                int c0 = wn + nf * 8 + g;
                bf[nf][0] = Bs[kk + tg    ][c0];
                bf[nf][1] = Bs[kk + tg + 4][c0];
            }
            #pragma unroll
            for (int mf = 0; mf < 4; mf++)
                #pragma unroll
                for (int nf = 0; nf < 8; nf++)
                    mma8(Creg[mf][nf], a[mf], bf[nf]);
        }
        __syncthreads();
    }
    #pragma unroll
    for (int mf = 0; mf < 4; mf++) {
        #pragma unroll
        for (int nf = 0; nf < 8; nf++) {
            int r = mt * 128 + wm + mf * 16 + g;
            int c = nt * 128 + wn + nf * 8 + tg * 2;
            float b0 = bias[c], b1 = bias[c + 1];
            out[(size_t)r * CH + c    ] = Creg[mf][nf][0] + b0;
            out[(size_t)r * CH + c + 1] = Creg[mf][nf][1] + b1;
            out[(size_t)(r + 8) * CH + c    ] = Creg[mf][nf][2] + b0;
            out[(size_t)(r + 8) * CH + c + 1] = Creg[mf][nf][3] + b1;
        }
    }
}

// =====================================================================
extern "C" void kernel_launch(void* const* d_in, const int* in_sizes, int n_in,
                              void* d_out, int out_size)
{
    const float* x     = (const float*)d_in[0];
    const float* sc    = (const float*)d_in[1];
    const float* Wqkv  = (const float*)d_in[2];
    const float* Wproj = (const float*)d_in[3];
    const float* bproj = (const float*)d_in[4];
    float* out = (float*)d_out;

    // QKV: M = 19520 -> 153 m-tiles, N = 2304 -> 18 n-tiles
    qkv_gemm<<<dim3(18, 153), 128>>>(x, sc, Wqkv);
    // attention: 16 q-tiles x 192 (b,h)
    attn_kernel<<<dim3(16, 192), 128>>>();
    // proj: M = 16384 -> 128 m-tiles, N = 768 -> 6 n-tiles
    proj_gemm<<<dim3(6, 128), 128>>>(Wproj, bproj, out);
}

// round 9
// speedup vs baseline: 26.4439x; 1.0397x over previous
#include <cuda_runtime.h>
#include <cstdint>

#define BATCH 16
#define SEQ   1024
#define CH    768
#define HEADS 12
#define DHEAD 64
#define NTOK  1220              // 1024 + 196
#define NKV   1280              // padded key count
#define MQKV  (BATCH*NTOK)      // 19520 rows of xt
#define QKVN  (3*CH)            // 2304

// ---------------- scratch (zero-initialized at module load; pad rows of K/V
// are never written so they stay 0.0; symbols referenced ONLY in device code)
__device__ float g_Q [BATCH*HEADS*SEQ *DHEAD];   // [b][h][t<1024][d]
__device__ float g_K [BATCH*HEADS*NKV *DHEAD];   // [b][h][t<1280][d]
__device__ float g_V [BATCH*HEADS*NKV *DHEAD];
__device__ float g_AT[BATCH*SEQ*CH];             // attention out [b*1024+t][h*64+d]

// ---------------- tf32 helpers ----------------
__device__ __forceinline__ unsigned f2t(float x){
    unsigned u; asm("cvt.rna.tf32.f32 %0, %1;" : "=r"(u) : "f"(x)); return u;
}
__device__ __forceinline__ void mma8(float* c, const unsigned* a, const unsigned* b){
    asm volatile("mma.sync.aligned.m16n8k8.row.col.f32.tf32.tf32.f32 "
        "{%0,%1,%2,%3}, {%4,%5,%6,%7}, {%8,%9}, {%0,%1,%2,%3};"
        : "+f"(c[0]), "+f"(c[1]), "+f"(c[2]), "+f"(c[3])
        : "r"(a[0]), "r"(a[1]), "r"(a[2]), "r"(a[3]), "r"(b[0]), "r"(b[1]));
}

// =====================================================================
// Kernel 1: QKV GEMM with register-prefetch pipelining.
// Block tile 128x128, k-tile 32, 4 warps of 64x64.
// Loop: LDG(kt+1)->regs ; MMA(kt) from smem ; sync ; STS ; sync.
// =====================================================================
__global__ __launch_bounds__(128, 2) void qkv_gemm(
    const float* __restrict__ x, const float* __restrict__ sc,
    const float* __restrict__ W)
{
    __shared__ unsigned As[128][36];   // [m][k]
    __shared__ unsigned Bs[32][132];   // [k][n]

    const int mt = blockIdx.y, nt = blockIdx.x;
    const int tid = threadIdx.x;
    const int wid = tid >> 5, lane = tid & 31;
    const int g = lane >> 2, tg = lane & 3;
    const int wm = (wid & 1) * 64, wn = (wid >> 1) * 64;

    // per-thread staging geometry (8 chunks of 16B per matrix)
    // A: row = (tid + i*128)>>3, kc = ((tid+i*128)&7)*4  -> row_a + i*16
    const int row_a = tid >> 3, kc_a = (tid & 7) * 4;
    const int row_b = tid >> 5, nc_b = (tid & 31) * 4;

    // A-row source pointers (xt mapping), computed once
    const float* asrc[8];
    bool aval[8];
    #pragma unroll
    for (int i = 0; i < 8; i++) {
        int gr = mt * 128 + row_a + i * 16;
        aval[i] = (gr < MQKV);
        if (aval[i]) {
            int b = gr / NTOK, t = gr - b * NTOK;
            asrc[i] = (t < SEQ) ? (x + (size_t)(b * SEQ + t) * CH)
                                : (sc + (size_t)(t - SEQ) * CH);
        } else {
            asrc[i] = x;   // dummy, never stored
        }
    }

    float4 pa[8], pb[8];
    auto ldg_tile = [&](int kt){
        const int kt0 = kt * 32;
        #pragma unroll
        for (int i = 0; i < 8; i++)
            pa[i] = aval[i] ? *(const float4*)(asrc[i] + kt0 + kc_a)
                            : make_float4(0.f, 0.f, 0.f, 0.f);
        #pragma unroll
        for (int i = 0; i < 8; i++)
            pb[i] = *(const float4*)(W + (size_t)(kt0 + row_b + i * 4) * QKVN
                                       + nt * 128 + nc_b);
    };
    auto sts_tile = [&](){
        #pragma unroll
        for (int i = 0; i < 8; i++)
            *(uint4*)&As[row_a + i * 16][kc_a] =
                make_uint4(f2t(pa[i].x), f2t(pa[i].y), f2t(pa[i].z), f2t(pa[i].w));
        #pragma unroll
        for (int i = 0; i < 8; i++)
            *(uint4*)&Bs[row_b + i * 4][nc_b] =
                make_uint4(f2t(pb[i].x), f2t(pb[i].y), f2t(pb[i].z), f2t(pb[i].w));
    };

    float Creg[4][8][4];
    #pragma unroll
    for (int i = 0; i < 4; i++)
        #pragma unroll
        for (int j = 0; j < 8; j++)
            #pragma unroll
            for (int e = 0; e < 4; e++) Creg[i][j][e] = 0.f;

    // prologue: tile 0
    ldg_tile(0);
    sts_tile();
    __syncthreads();

    constexpr int NKT = CH / 32;   // 24
    for (int kt = 0; kt < NKT; kt++) {
        if (kt + 1 < NKT) ldg_tile(kt + 1);    // in flight during compute
        // ---- compute tile kt ----
        #pragma unroll
        for (int ks = 0; ks < 4; ks++) {
            const int kk = ks * 8;
            unsigned a[4][4];
            #pragma unroll
            for (int mf = 0; mf < 4; mf++) {
                int r0 = wm + mf * 16 + g;
                a[mf][0] = As[r0    ][kk + tg];
                a[mf][1] = As[r0 + 8][kk + tg];
                a[mf][2] = As[r0    ][kk + tg + 4];
                a[mf][3] = As[r0 + 8][kk + tg + 4];
            }
            unsigned bf[8][2];
            #pragma unroll
            for (int nf = 0; nf < 8; nf++) {
                int c0 = wn + nf * 8 + g;
                bf[nf][0] = Bs[kk + tg    ][c0];
                bf[nf][1] = Bs[kk + tg + 4][c0];
            }
            #pragma unroll
            for (int mf = 0; mf < 4; mf++)
                #pragma unroll
                for (int nf = 0; nf < 8; nf++)
                    mma8(Creg[mf][nf], a[mf], bf[nf]);
        }
        __syncthreads();                       // all reads of smem done
        if (kt + 1 < NKT) { sts_tile(); }      // overwrite with tile kt+1
        __syncthreads();                       // writes visible
    }

    // ---- epilogue: scatter into Q/K/V ----
    #pragma unroll
    for (int mf = 0; mf < 4; mf++) {
        #pragma unroll
        for (int nf = 0; nf < 8; nf++) {
            #pragma unroll
            for (int e = 0; e < 4; e++) {
                int r = mt * 128 + wm + mf * 16 + g + ((e >= 2) ? 8 : 0);
                int c = nt * 128 + wn + nf * 8 + tg * 2 + (e & 1);
                if (r >= MQKV) continue;
                int b = r / NTOK, t = r - b * NTOK;
                int which = c / CH, cc = c - which * CH;
                int h = cc >> 6, d = cc & 63;
                float v = Creg[mf][nf][e];
                if (which == 0) {
                    if (t < SEQ) g_Q[((size_t)(b * HEADS + h) * SEQ + t) * DHEAD + d] = v;
                } else if (which == 1) {
                    g_K[((size_t)(b * HEADS + h) * NKV + t) * DHEAD + d] = v;
                } else {
                    g_V[((size_t)(b * HEADS + h) * NKV + t) * DHEAD + d] = v;
                }
            }
        }
    }
}

// =====================================================================
// Kernel 2: flash attention — byte-identical to proven round-1 kernel.
// =====================================================================
__global__ __launch_bounds__(128) void attn_kernel()
{
    __shared__ unsigned Ks[64][72];
    __shared__ unsigned Vs[64][72];

    const int bh = blockIdx.y, qt = blockIdx.x;
    const int b = bh / HEADS, h = bh - b * HEADS;
    const int tid = threadIdx.x;
    const int w = tid >> 5, lane = tid & 31;
    const int g = lane >> 2, tg = lane & 3;

    const float* Qp = g_Q + (size_t)bh * SEQ * DHEAD;
    const float* Kp = g_K + (size_t)bh * NKV * DHEAD;
    const float* Vp = g_V + (size_t)bh * NKV * DHEAD;
    const int q0 = qt * 64 + w * 16;

    unsigned aq[8][4];
    #pragma unroll
    for (int ks = 0; ks < 8; ks++) {
        aq[ks][0] = f2t(Qp[(size_t)(q0 + g    ) * DHEAD + ks * 8 + tg    ]);
        aq[ks][1] = f2t(Qp[(size_t)(q0 + g + 8) * DHEAD + ks * 8 + tg    ]);
        aq[ks][2] = f2t(Qp[(size_t)(q0 + g    ) * DHEAD + ks * 8 + tg + 4]);
        aq[ks][3] = f2t(Qp[(size_t)(q0 + g + 8) * DHEAD + ks * 8 + tg + 4]);
    }

    float O[8][4];
    #pragma unroll
    for (int i = 0; i < 8; i++)
        #pragma unroll
        for (int e = 0; e < 4; e++) O[i][e] = 0.f;
    float mrow[2] = { -1e30f, -1e30f };
    float lrow[2] = { 0.f, 0.f };

    for (int kt = 0; kt < NKV / 64; kt++) {
        const int j0 = kt * 64;
        #pragma unroll
        for (int i = 0; i < 8; i++) {
            int slot = tid + i * 128;
            int row = slot >> 4, c4 = (slot & 15) * 4;
            float4 kv = *(const float4*)(Kp + (size_t)(j0 + row) * DHEAD + c4);
            *(uint4*)&Ks[row][c4] = make_uint4(f2t(kv.x), f2t(kv.y), f2t(kv.z), f2t(kv.w));
            float4 vv = *(const float4*)(Vp + (size_t)(j0 + row) * DHEAD + c4);
            *(uint4*)&Vs[row][c4] = make_uint4(f2t(vv.x), f2t(vv.y), f2t(vv.z), f2t(vv.w));
        }
        __syncthreads();

        float S[8][4];
        #pragma unroll
        for (int i = 0; i < 8; i++)
            #pragma unroll
            for (int e = 0; e < 4; e++) S[i][e] = 0.f;
        #pragma unroll
        for (int nf = 0; nf < 8; nf++) {
            #pragma unroll
            for (int ks = 0; ks < 8; ks++) {
                unsigned bb[2];
                bb[0] = Ks[nf * 8 + g][ks * 8 + tg    ];
                bb[1] = Ks[nf * 8 + g][ks * 8 + tg + 4];
                mma8(S[nf], aq[ks], bb);
            }
        }
        __syncthreads();

        #pragma unroll
        for (int nf = 0; nf < 8; nf++) {
            #pragma unroll
            for (int e = 0; e < 4; e++) {
                float s = S[nf][e] * 0.125f;
                int j = j0 + nf * 8 + tg * 2 + (e & 1);
                if (j >= NTOK) s = -1e30f;
                S[nf][e] = s;
            }
        }
        #pragma unroll
        for (int r = 0; r < 2; r++) {
            float mx = -1e30f;
            #pragma unroll
            for (int nf = 0; nf < 8; nf++) {
                mx = fmaxf(mx, S[nf][2 * r]);
                mx = fmaxf(mx, S[nf][2 * r + 1]);
            }
            mx = fmaxf(mx, __shfl_xor_sync(0xffffffffu, mx, 1));
            mx = fmaxf(mx, __shfl_xor_sync(0xffffffffu, mx, 2));
            float mnew = fmaxf(mrow[r], mx);
            float alpha = __expf(mrow[r] - mnew);
            float sum = 0.f;
            #pragma unroll
            for (int nf = 0; nf < 8; nf++) {
                float p0 = __expf(S[nf][2 * r    ] - mnew);
                float p1 = __expf(S[nf][2 * r + 1] - mnew);
                S[nf][2 * r] = p0; S[nf][2 * r + 1] = p1;
                sum += p0 + p1;
            }
            sum += __shfl_xor_sync(0xffffffffu, sum, 1);
            sum += __shfl_xor_sync(0xffffffffu, sum, 2);
            lrow[r] = lrow[r] * alpha + sum;
            mrow[r] = mnew;
            #pragma unroll
            for (int nf = 0; nf < 8; nf++) {
                O[nf][2 * r] *= alpha; O[nf][2 * r + 1] *= alpha;
            }
        }
        #pragma unroll
        for (int nf = 0; nf < 8; nf++) {
            Ks[w * 16 + g    ][nf * 8 + tg * 2    ] = f2t(S[nf][0]);
            Ks[w * 16 + g    ][nf * 8 + tg * 2 + 1] = f2t(S[nf][1]);
            Ks[w * 16 + g + 8][nf * 8 + tg * 2    ] = f2t(S[nf][2]);
            Ks[w * 16 + g + 8][nf * 8 + tg * 2 + 1] = f2t(S[nf][3]);
        }
        __syncwarp();
        #pragma unroll
        for (int ks = 0; ks < 8; ks++) {
            unsigned ap[4];
            ap[0] = Ks[w * 16 + g    ][ks * 8 + tg    ];
            ap[1] = Ks[w * 16 + g + 8][ks * 8 + tg    ];
            ap[2] = Ks[w * 16 + g    ][ks * 8 + tg + 4];
            ap[3] = Ks[w * 16 + g + 8][ks * 8 + tg + 4];
            #pragma unroll
            for (int nf = 0; nf < 8; nf++) {
                unsigned bb[2];
                bb[0] = Vs[ks * 8 + tg    ][nf * 8 + g];
                bb[1] = Vs[ks * 8 + tg + 4][nf * 8 + g];
                mma8(O[nf], ap, bb);
            }
        }
        __syncthreads();
    }
    float inv0 = 1.f / lrow[0], inv1 = 1.f / lrow[1];
    int row0 = b * SEQ + qt * 64 + w * 16 + g;
    #pragma unroll
    for (int nf = 0; nf < 8; nf++) {
        int col = h * DHEAD + nf * 8 + tg * 2;
        g_AT[(size_t)row0 * CH + col    ] = O[nf][0] * inv0;
        g_AT[(size_t)row0 * CH + col + 1] = O[nf][1] * inv0;
        g_AT[(size_t)(row0 + 8) * CH + col    ] = O[nf][2] * inv1;
        g_AT[(size_t)(row0 + 8) * CH + col + 1] = O[nf][3] * inv1;
    }
}

// =====================================================================
// Kernel 3: proj GEMM + bias, same prefetch pipelining.
// =====================================================================
__global__ __launch_bounds__(128, 2) void proj_gemm(
    const float* __restrict__ W, const float* __restrict__ bias,
    float* __restrict__ out)
{
    __shared__ unsigned As[128][36];
    __shared__ unsigned Bs[32][132];

    const int mt = blockIdx.y, nt = blockIdx.x;
    const int tid = threadIdx.x;
    const int wid = tid >> 5, lane = tid & 31;
    const int g = lane >> 2, tg = lane & 3;
    const int wm = (wid & 1) * 64, wn = (wid >> 1) * 64;

    const int row_a = tid >> 3, kc_a = (tid & 7) * 4;
    const int row_b = tid >> 5, nc_b = (tid & 31) * 4;

    float4 pa[8], pb[8];
    auto ldg_tile = [&](int kt){
        const int kt0 = kt * 32;
        #pragma unroll
        for (int i = 0; i < 8; i++)
            pa[i] = *(const float4*)(g_AT + (size_t)(mt * 128 + row_a + i * 16) * CH
                                          + kt0 + kc_a);
        #pragma unroll
        for (int i = 0; i < 8; i++)
            pb[i] = *(const float4*)(W + (size_t)(kt0 + row_b + i * 4) * CH
                                       + nt * 128 + nc_b);
    };
    auto sts_tile = [&](){
        #pragma unroll
        for (int i = 0; i < 8; i++)
            *(uint4*)&As[row_a + i * 16][kc_a] =
                make_uint4(f2t(pa[i].x), f2t(pa[i].y), f2t(pa[i].z), f2t(pa[i].w));
        #pragma unroll
        for (int i = 0; i < 8; i++)
            *(uint4*)&Bs[row_b + i * 4][nc_b] =
                make_uint4(f2t(pb[i].x), f2t(pb[i].y), f2t(pb[i].z), f2t(pb[i].w));
    };

    float Creg[4][8][4];
    #pragma unroll
    for (int i = 0; i < 4; i++)
        #pragma unroll
        for (int j = 0; j < 8; j++)
            #pragma unroll
            for (int e = 0; e < 4; e++) Creg[i][j][e] = 0.f;

    ldg_tile(0);
    sts_tile();
    __syncthreads();

    constexpr int NKT = CH / 32;
    for (int kt = 0; kt < NKT; kt++) {
        if (kt + 1 < NKT) ldg_tile(kt + 1);
        #pragma unroll
        for (int ks = 0; ks < 4; ks++) {
            const int kk = ks * 8;
            unsigned a[4][4];
            #pragma unroll
            for (int mf = 0; mf < 4; mf++) {
                int r0 = wm + mf * 16 + g;
                a[mf][0] = As[r0    ][kk + tg];
                a[mf][1] = As[r0 + 8][kk + tg];
                a[mf][2] = As[r0    ][kk + tg + 4];
                a[mf][3] = As[r0 + 8][kk + tg + 4];
            }
            unsigned bf[8][2];
            #pragma unroll
            for (int nf = 0; nf < 8; nf++) {
                int c0 = wn + nf * 8 + g;
                bf[nf][0] = Bs[kk + tg    ][c0];
                bf[nf][1] = Bs[kk + tg + 4][c0];
            }
            #pragma unroll
            for (int mf = 0; mf < 4; mf++)
                #pragma unroll
                for (int nf = 0; nf < 8; nf++)
                    mma8(Creg[mf][nf], a[mf], bf[nf]);
        }
        __syncthreads();
        if (kt + 1 < NKT) { sts_tile(); }
        __syncthreads();
    }

    #pragma unroll
    for (int mf = 0; mf < 4; mf++) {
        #pragma unroll
        for (int nf = 0; nf < 8; nf++) {
            int r = mt * 128 + wm + mf * 16 + g;
            int c = nt * 128 + wn + nf * 8 + tg * 2;
            float b0 = bias[c], b1 = bias[c + 1];
            out[(size_t)r * CH + c    ] = Creg[mf][nf][0] + b0;
            out[(size_t)r * CH + c + 1] = Creg[mf][nf][1] + b1;
            out[(size_t)(r + 8) * CH + c    ] = Creg[mf][nf][2] + b0;
            out[(size_t)(r + 8) * CH + c + 1] = Creg[mf][nf][3] + b1;
        }
    }
}

// =====================================================================
extern "C" void kernel_launch(void* const* d_in, const int* in_sizes, int n_in,
                              void* d_out, int out_size)
{
    const float* x     = (const float*)d_in[0];
    const float* sc    = (const float*)d_in[1];
    const float* Wqkv  = (const float*)d_in[2];
    const float* Wproj = (const float*)d_in[3];
    const float* bproj = (const float*)d_in[4];
    float* out = (float*)d_out;

    // QKV: M = 19520 -> 153 m-tiles, N = 2304 -> 18 n-tiles
    qkv_gemm<<<dim3(18, 153), 128>>>(x, sc, Wqkv);
    // attention: 16 q-tiles x 192 (b,h)
    attn_kernel<<<dim3(16, 192), 128>>>();
    // proj: M = 16384 -> 128 m-tiles, N = 768 -> 6 n-tiles
    proj_gemm<<<dim3(6, 128), 128>>>(Wproj, bproj, out);
}

// round 10
// speedup vs baseline: 29.8957x; 1.1305x over previous
#include <cuda_runtime.h>
#include <cstdint>

#define BATCH 16
#define SEQ   1024
#define CH    768
#define HEADS 12
#define DHEAD 64
#define NTOK  1220              // 1024 + 196
#define NKV   1280              // padded key count
#define MQKV  (BATCH*NTOK)      // 19520 rows of xt
#define MPAD  19584             // 153*128 (padded M for qkv)
#define QKVN  (3*CH)            // 2304

// ---------------- scratch (zero-initialized at module load). RULE: these
// symbols are referenced ONLY inside device code (never as kernel args). ----
__device__ float g_XT[MPAD*CH];                  // xt, tf32-rounded; pad rows 0
__device__ float g_W1[CH*QKVN];                  // W_qkv, tf32-rounded
__device__ float g_W2[CH*CH];                    // W_proj, tf32-rounded
__device__ float g_Q [BATCH*HEADS*SEQ *DHEAD];   // tf32-rounded
__device__ float g_K [BATCH*HEADS*NKV *DHEAD];   // tf32-rounded; pad rows 0
__device__ float g_V [BATCH*HEADS*NKV *DHEAD];   // tf32-rounded
__device__ float g_AT[BATCH*SEQ*CH];             // attn out, tf32-rounded

// ---------------- helpers ----------------
__device__ __forceinline__ unsigned f2t(float x){
    unsigned u; asm("cvt.rna.tf32.f32 %0, %1;" : "=r"(u) : "f"(x)); return u;
}
__device__ __forceinline__ float tf32r(float x){
    unsigned u; asm("cvt.rna.tf32.f32 %0, %1;" : "=r"(u) : "f"(x));
    return __uint_as_float(u);
}
__device__ __forceinline__ void mma8(float* c, const unsigned* a, const unsigned* b){
    asm volatile("mma.sync.aligned.m16n8k8.row.col.f32.tf32.tf32.f32 "
        "{%0,%1,%2,%3}, {%4,%5,%6,%7}, {%8,%9}, {%0,%1,%2,%3};"
        : "+f"(c[0]), "+f"(c[1]), "+f"(c[2]), "+f"(c[3])
        : "r"(a[0]), "r"(a[1]), "r"(a[2]), "r"(a[3]), "r"(b[0]), "r"(b[1]));
}
__device__ __forceinline__ uint32_t smem_u32(const void* p){
    uint32_t a;
    asm("{ .reg .u64 t; cvta.to.shared.u64 t, %1; cvt.u32.u64 %0, t; }" : "=r"(a) : "l"(p));
    return a;
}
__device__ __forceinline__ void cpa16(uint32_t dst, const float* src){
    asm volatile("cp.async.cg.shared.global [%0], [%1], 16;" :: "r"(dst), "l"(src) : "memory");
}
__device__ __forceinline__ void cp_commit(){
    asm volatile("cp.async.commit_group;" ::: "memory");
}
__device__ __forceinline__ void cp_wait0(){
    asm volatile("cp.async.wait_group 0;" ::: "memory");
}
__device__ __forceinline__ void cp_wait1(){
    asm volatile("cp.async.wait_group 1;" ::: "memory");
}

// =====================================================================
// Prep A: materialize xt rows into g_XT, tf32-rounded.
// =====================================================================
__global__ __launch_bounds__(256) void xt_copy(
    const float* __restrict__ x, const float* __restrict__ sc)
{
    size_t i = (size_t)blockIdx.x * blockDim.x + threadIdx.x;   // float4 idx
    size_t tot = (size_t)MQKV * (CH/4);
    if (i >= tot) return;
    int row = (int)(i / (CH/4));
    int c4  = (int)(i % (CH/4)) * 4;
    int b = row / NTOK, t = row - b * NTOK;
    const float* src = (t < SEQ) ? (x + (size_t)(b * SEQ + t) * CH)
                                 : (sc + (size_t)(t - SEQ) * CH);
    float4 v = *(const float4*)(src + c4);
    *(float4*)(g_XT + (size_t)row * CH + c4) =
        make_float4(tf32r(v.x), tf32r(v.y), tf32r(v.z), tf32r(v.w));
}

// =====================================================================
// Prep B: tf32-round weights into g_W1 / g_W2 (dst chosen in device code)
// =====================================================================
template<int WHICH>
__global__ __launch_bounds__(256) void w_round(const float* __restrict__ src, int n4)
{
    int i = blockIdx.x * 256 + threadIdx.x;
    if (i >= n4) return;
    float* dst = WHICH ? g_W2 : g_W1;
    float4 v = *(const float4*)(src + (size_t)i * 4);
    *(float4*)(dst + (size_t)i * 4) =
        make_float4(tf32r(v.x), tf32r(v.y), tf32r(v.z), tf32r(v.w));
}

// =====================================================================
// GEMM v3: 128x128 block tile, 4 warps of 64x64, k-tile 32.
// 3-stage cp.async pipeline, ONE __syncthreads per k-tile
// (issue-after-sync ordering; wait_group 1 keeps 2 tiles in flight).
// Strides: A 36 (conflict-free), B 136 (conflict-free, fixed from 132).
// MODE 0: A=g_XT, B=g_W1, scatter into g_Q/g_K/g_V (tf32-rounded)
// MODE 1: A=g_AT, B=g_W2, out = C + bias
// =====================================================================
#define AW 36
#define BW 136
#define STGW (128*AW + 32*BW)    // 4608 + 4352 = 8960 words
#define NSTG 3
#define GSM (NSTG*STGW*4)        // 107520 B

template<int MODE>
__global__ __launch_bounds__(128, 2)
void gemm3(float* __restrict__ out, const float* __restrict__ bias)
{
    constexpr int NKT = CH / 32;   // 24
    extern __shared__ unsigned sm[];

    const float* A   = (MODE == 0) ? g_XT : g_AT;
    const float* B   = (MODE == 0) ? g_W1 : g_W2;
    const int    ldb = (MODE == 0) ? QKVN : CH;

    const int tid = threadIdx.x, wid = tid >> 5, lane = tid & 31;
    const int g = lane >> 2, tg = lane & 3;
    const int mt = blockIdx.y, nt = blockIdx.x;
    const int wm = (wid & 1) * 64, wn = (wid >> 1) * 64;

    const int row_a = tid >> 3, kc_a = (tid & 7) * 4;
    const int row_b = tid >> 5, nc_b = (tid & 31) * 4;
    const uint32_t sb = smem_u32(sm);

    auto issue = [&](int kt){
        const int s = kt % NSTG;
        const int kt0 = kt * 32;
        uint32_t ab = sb + (uint32_t)(s * STGW) * 4u;
        uint32_t bb = ab + 128u * AW * 4u;
        #pragma unroll
        for (int i = 0; i < 8; i++) {
            int r = row_a + i * 16;
            cpa16(ab + (uint32_t)(r * AW + kc_a) * 4u,
                  A + (size_t)(mt * 128 + r) * CH + kt0 + kc_a);
        }
        #pragma unroll
        for (int i = 0; i < 8; i++) {
            int r = row_b + i * 4;
            cpa16(bb + (uint32_t)(r * BW + nc_b) * 4u,
                  B + (size_t)(kt0 + r) * ldb + nt * 128 + nc_b);
        }
        cp_commit();
    };

    float C[4][8][4];
    #pragma unroll
    for (int i = 0; i < 4; i++)
        #pragma unroll
        for (int j = 0; j < 8; j++)
            #pragma unroll
            for (int e = 0; e < 4; e++) C[i][j][e] = 0.f;

    issue(0);
    issue(1);

    for (int kt = 0; kt < NKT; kt++) {
        cp_wait1();                 // tile kt landed (own view)
        __syncthreads();            // visibility + closes reads of buf (kt)%3's prior tenant
        if (kt + 2 < NKT) issue(kt + 2);   // safe: after sync, all done reading tile kt-1
        else cp_commit();                  // empty group keeps accounting uniform

        const unsigned* As = sm + (kt % NSTG) * STGW;
        const unsigned* Bs = As + 128 * AW;
        #pragma unroll
        for (int ks = 0; ks < 4; ks++) {
            const int kk = ks * 8;
            unsigned a[4][4];
            #pragma unroll
            for (int mf = 0; mf < 4; mf++) {
                int r0 = wm + mf * 16 + g;
                a[mf][0] = As[(r0    ) * AW + kk + tg];
                a[mf][1] = As[(r0 + 8) * AW + kk + tg];
                a[mf][2] = As[(r0    ) * AW + kk + tg + 4];
                a[mf][3] = As[(r0 + 8) * AW + kk + tg + 4];
            }
            unsigned bf[8][2];
            #pragma unroll
            for (int nf = 0; nf < 8; nf++) {
                int c0 = wn + nf * 8 + g;
                bf[nf][0] = Bs[(kk + tg    ) * BW + c0];
                bf[nf][1] = Bs[(kk + tg + 4) * BW + c0];
            }
            #pragma unroll
            for (int mf = 0; mf < 4; mf++)
                #pragma unroll
                for (int nf = 0; nf < 8; nf++)
                    mma8(C[mf][nf], a[mf], bf[nf]);
        }
    }

    // ---- epilogue ----
    #pragma unroll
    for (int mf = 0; mf < 4; mf++) {
        #pragma unroll
        for (int nf = 0; nf < 8; nf++) {
            #pragma unroll
            for (int e = 0; e < 4; e++) {
                int r = mt * 128 + wm + mf * 16 + g + ((e >= 2) ? 8 : 0);
                int c = nt * 128 + wn + nf * 8 + tg * 2 + (e & 1);
                float v = C[mf][nf][e];
                if (MODE == 1) {
                    out[(size_t)r * CH + c] = v + bias[c];
                } else {
                    if (r >= MQKV) continue;
                    int b = r / NTOK, t = r - b * NTOK;
                    int wc = c / CH, cc = c - wc * CH;
                    int h = cc >> 6, d = cc & 63;
                    float vr = tf32r(v);
                    if (wc == 0) {
                        if (t < SEQ)
                            g_Q[((size_t)(b * HEADS + h) * SEQ + t) * DHEAD + d] = vr;
                    } else if (wc == 1) {
                        g_K[((size_t)(b * HEADS + h) * NKV + t) * DHEAD + d] = vr;
                    } else {
                        g_V[((size_t)(b * HEADS + h) * NKV + t) * DHEAD + d] = vr;
                    }
                }
            }
        }
    }
}

// =====================================================================
// Attention v3: round-1 dataflow; upgrades: cp.async K/V staging
// (pre-rounded tf32), raw-bit Q fragment loads, conflict-free strides
// (K/P stride 76, V stride 72). grid = (16 q-tiles, 192 bh), 4 warps.
// =====================================================================
__global__ __launch_bounds__(128) void attn_k()
{
    __shared__ unsigned Ks[64][76];   // K tile, then reused for P
    __shared__ unsigned Vs[64][72];

    const int bh = blockIdx.y, qt = blockIdx.x;
    const int b = bh / HEADS, h = bh - b * HEADS;
    const int tid = threadIdx.x;
    const int w = tid >> 5, lane = tid & 31;
    const int g = lane >> 2, tg = lane & 3;

    const unsigned* Qu = (const unsigned*)g_Q + (size_t)bh * SEQ * DHEAD;
    const float* Kp = g_K + (size_t)bh * NKV * DHEAD;
    const float* Vp = g_V + (size_t)bh * NKV * DHEAD;
    const uint32_t ksb = smem_u32(Ks);
    const uint32_t vsb = smem_u32(Vs);
    const int q0 = qt * 64 + w * 16;

    // Q fragments: pre-rounded tf32 bit patterns, no cvt needed
    unsigned aq[8][4];
    #pragma unroll
    for (int ks = 0; ks < 8; ks++) {
        aq[ks][0] = Qu[(size_t)(q0 + g    ) * DHEAD + ks * 8 + tg    ];
        aq[ks][1] = Qu[(size_t)(q0 + g + 8) * DHEAD + ks * 8 + tg    ];
        aq[ks][2] = Qu[(size_t)(q0 + g    ) * DHEAD + ks * 8 + tg + 4];
        aq[ks][3] = Qu[(size_t)(q0 + g + 8) * DHEAD + ks * 8 + tg + 4];
    }

    float O[8][4];
    #pragma unroll
    for (int i = 0; i < 8; i++)
        #pragma unroll
        for (int e = 0; e < 4; e++) O[i][e] = 0.f;
    float mrow[2] = { -1e30f, -1e30f };
    float lrow[2] = { 0.f, 0.f };

    for (int kt = 0; kt < NKV / 64; kt++) {
        const int j0 = kt * 64;
        // ---- stage K,V via cp.async (16 x 16B chunks per thread) ----
        #pragma unroll
        for (int i = 0; i < 8; i++) {
            int ci = tid + i * 128;
            int row = ci >> 4, c4 = (ci & 15) * 4;
            cpa16(ksb + (uint32_t)(row * 76 + c4) * 4u,
                  Kp + (size_t)(j0 + row) * DHEAD + c4);
        }
        #pragma unroll
        for (int i = 0; i < 8; i++) {
            int ci = tid + i * 128;
            int row = ci >> 4, c4 = (ci & 15) * 4;
            cpa16(vsb + (uint32_t)(row * 72 + c4) * 4u,
                  Vp + (size_t)(j0 + row) * DHEAD + c4);
        }
        cp_commit();
        cp_wait0();
        __syncthreads();

        // ---- S = Q @ K^T ----
        float S[8][4];
        #pragma unroll
        for (int i = 0; i < 8; i++)
            #pragma unroll
            for (int e = 0; e < 4; e++) S[i][e] = 0.f;
        #pragma unroll
        for (int nf = 0; nf < 8; nf++) {
            #pragma unroll
            for (int ks = 0; ks < 8; ks++) {
                unsigned bb[2];
                bb[0] = Ks[nf * 8 + g][ks * 8 + tg    ];
                bb[1] = Ks[nf * 8 + g][ks * 8 + tg + 4];
                mma8(S[nf], aq[ks], bb);
            }
        }
        __syncthreads();   // all S-reads of Ks done before it becomes P

        // ---- scale + mask ----
        #pragma unroll
        for (int nf = 0; nf < 8; nf++) {
            #pragma unroll
            for (int e = 0; e < 4; e++) {
                float s = S[nf][e] * 0.125f;
                int j = j0 + nf * 8 + tg * 2 + (e & 1);
                if (j >= NTOK) s = -1e30f;
                S[nf][e] = s;
            }
        }
        // ---- online softmax ----
        #pragma unroll
        for (int r = 0; r < 2; r++) {
            float mx = -1e30f;
            #pragma unroll
            for (int nf = 0; nf < 8; nf++) {
                mx = fmaxf(mx, S[nf][2 * r]);
                mx = fmaxf(mx, S[nf][2 * r + 1]);
            }
            mx = fmaxf(mx, __shfl_xor_sync(0xffffffffu, mx, 1));
            mx = fmaxf(mx, __shfl_xor_sync(0xffffffffu, mx, 2));
            float mnew = fmaxf(mrow[r], mx);
            float alpha = __expf(mrow[r] - mnew);
            float sum = 0.f;
            #pragma unroll
            for (int nf = 0; nf < 8; nf++) {
                float p0 = __expf(S[nf][2 * r    ] - mnew);
                float p1 = __expf(S[nf][2 * r + 1] - mnew);
                S[nf][2 * r] = p0; S[nf][2 * r + 1] = p1;
                sum += p0 + p1;
            }
            sum += __shfl_xor_sync(0xffffffffu, sum, 1);
            sum += __shfl_xor_sync(0xffffffffu, sum, 2);
            lrow[r] = lrow[r] * alpha + sum;
            mrow[r] = mnew;
            #pragma unroll
            for (int nf = 0; nf < 8; nf++) {
                O[nf][2 * r] *= alpha; O[nf][2 * r + 1] *= alpha;
            }
        }
        // ---- store P into Ks (warp-private 16 rows) ----
        #pragma unroll
        for (int nf = 0; nf < 8; nf++) {
            Ks[w * 16 + g    ][nf * 8 + tg * 2    ] = f2t(S[nf][0]);
            Ks[w * 16 + g    ][nf * 8 + tg * 2 + 1] = f2t(S[nf][1]);
            Ks[w * 16 + g + 8][nf * 8 + tg * 2    ] = f2t(S[nf][2]);
            Ks[w * 16 + g + 8][nf * 8 + tg * 2 + 1] = f2t(S[nf][3]);
        }
        __syncwarp();
        // ---- O += P @ V ----
        #pragma unroll
        for (int ks = 0; ks < 8; ks++) {
            unsigned ap[4];
            ap[0] = Ks[w * 16 + g    ][ks * 8 + tg    ];
            ap[1] = Ks[w * 16 + g + 8][ks * 8 + tg    ];
            ap[2] = Ks[w * 16 + g    ][ks * 8 + tg + 4];
            ap[3] = Ks[w * 16 + g + 8][ks * 8 + tg + 4];
            #pragma unroll
            for (int nf = 0; nf < 8; nf++) {
                unsigned bb[2];
                bb[0] = Vs[ks * 8 + tg    ][nf * 8 + g];
                bb[1] = Vs[ks * 8 + tg + 4][nf * 8 + g];
                mma8(O[nf], ap, bb);
            }
        }
        __syncthreads();   // before next tile's cp.async overwrites Ks/Vs
    }
    // ---- normalize, tf32-round (proj stages this raw), write g_AT ----
    float inv0 = 1.f / lrow[0], inv1 = 1.f / lrow[1];
    int row0 = b * SEQ + qt * 64 + w * 16 + g;
    #pragma unroll
    for (int nf = 0; nf < 8; nf++) {
        int col = h * DHEAD + nf * 8 + tg * 2;
        g_AT[(size_t)row0 * CH + col    ] = tf32r(O[nf][0] * inv0);
        g_AT[(size_t)row0 * CH + col + 1] = tf32r(O[nf][1] * inv0);
        g_AT[(size_t)(row0 + 8) * CH + col    ] = tf32r(O[nf][2] * inv1);
        g_AT[(size_t)(row0 + 8) * CH + col + 1] = tf32r(O[nf][3] * inv1);
    }
}

// =====================================================================
extern "C" void kernel_launch(void* const* d_in, const int* in_sizes, int n_in,
                              void* d_out, int out_size)
{
    const float* x     = (const float*)d_in[0];
    const float* sc    = (const float*)d_in[1];
    const float* Wqkv  = (const float*)d_in[2];
    const float* Wproj = (const float*)d_in[3];
    const float* bproj = (const float*)d_in[4];
    float* out = (float*)d_out;

    cudaFuncSetAttribute(gemm3<0>, cudaFuncAttributeMaxDynamicSharedMemorySize, GSM);
    cudaFuncSetAttribute(gemm3<1>, cudaFuncAttributeMaxDynamicSharedMemorySize, GSM);

    // prep: tf32-rounded xt + weights
    {
        size_t tot = (size_t)MQKV * (CH / 4);
        xt_copy<<<(unsigned)((tot + 255) / 256), 256>>>(x, sc);
    }
    w_round<0><<<(CH * QKVN / 4 + 255) / 256, 256>>>(Wqkv, CH * QKVN / 4);
    w_round<1><<<(CH * CH / 4 + 255) / 256, 256>>>(Wproj, CH * CH / 4);

    // qkv: M=19584 (153 m-tiles), N=2304 (18 n-tiles)
    gemm3<0><<<dim3(18, 153), 128, GSM>>>(nullptr, nullptr);
    // attention: 16 q-tiles x 192 (b,h)
    attn_k<<<dim3(16, 192), 128>>>();
    // proj: M=16384 (128 m-tiles), N=768 (6 n-tiles)
    gemm3<1><<<dim3(6, 128), 128, GSM>>>(out, bproj);
}

// round 11
// speedup vs baseline: 30.6549x; 1.0254x over previous
#include <cuda_runtime.h>
#include <cstdint>

#define BATCH 16
#define SEQ   1024
#define CH    768
#define HEADS 12
#define DHEAD 64
#define NTOK  1220              // 1024 + 196
#define NKV   1280              // padded key count
#define MQKV  (BATCH*NTOK)      // 19520 rows of xt
#define MPAD  19584             // 153*128
#define QKVN  (3*CH)            // 2304

// ---------------- scratch (zero-initialized). RULE: referenced ONLY in
// device code, never passed as kernel arguments. ----------------------------
__device__ float g_XT[MPAD*CH];                  // xt, tf32-rounded; pad rows 0
__device__ float g_W1[CH*QKVN];                  // W_qkv, tf32-rounded
__device__ float g_W2[CH*CH];                    // W_proj, tf32-rounded
__device__ float g_Q [BATCH*HEADS*SEQ *DHEAD];   // tf32-rounded
__device__ float g_K [BATCH*HEADS*NKV *DHEAD];   // tf32-rounded; pad rows 0
__device__ float g_V [BATCH*HEADS*NKV *DHEAD];   // tf32-rounded
__device__ float g_AT[BATCH*SEQ*CH];             // attn out, tf32-rounded

// ---------------- helpers ----------------
__device__ __forceinline__ unsigned f2t(float x){
    unsigned u; asm("cvt.rna.tf32.f32 %0, %1;" : "=r"(u) : "f"(x)); return u;
}
__device__ __forceinline__ float tf32r(float x){
    unsigned u; asm("cvt.rna.tf32.f32 %0, %1;" : "=r"(u) : "f"(x));
    return __uint_as_float(u);
}
__device__ __forceinline__ void mma8(float* c, const unsigned* a, const unsigned* b){
    asm volatile("mma.sync.aligned.m16n8k8.row.col.f32.tf32.tf32.f32 "
        "{%0,%1,%2,%3}, {%4,%5,%6,%7}, {%8,%9}, {%0,%1,%2,%3};"
        : "+f"(c[0]), "+f"(c[1]), "+f"(c[2]), "+f"(c[3])
        : "r"(a[0]), "r"(a[1]), "r"(a[2]), "r"(a[3]), "r"(b[0]), "r"(b[1]));
}
__device__ __forceinline__ uint32_t smem_u32(const void* p){
    uint32_t a;
    asm("{ .reg .u64 t; cvta.to.shared.u64 t, %1; cvt.u32.u64 %0, t; }" : "=r"(a) : "l"(p));
    return a;
}
__device__ __forceinline__ void cpa16(uint32_t dst, const float* src){
    asm volatile("cp.async.cg.shared.global [%0], [%1], 16;" :: "r"(dst), "l"(src) : "memory");
}
__device__ __forceinline__ void cp_commit(){
    asm volatile("cp.async.commit_group;" ::: "memory");
}
__device__ __forceinline__ void cp_wait0(){
    asm volatile("cp.async.wait_group 0;" ::: "memory");
}
__device__ __forceinline__ void cp_wait1(){
    asm volatile("cp.async.wait_group 1;" ::: "memory");
}

// =====================================================================
// Prep A: materialize xt rows, tf32-rounded
// =====================================================================
__global__ __launch_bounds__(256) void xt_copy(
    const float* __restrict__ x, const float* __restrict__ sc)
{
    size_t i = (size_t)blockIdx.x * blockDim.x + threadIdx.x;
    size_t tot = (size_t)MQKV * (CH/4);
    if (i >= tot) return;
    int row = (int)(i / (CH/4));
    int c4  = (int)(i % (CH/4)) * 4;
    int b = row / NTOK, t = row - b * NTOK;
    const float* src = (t < SEQ) ? (x + (size_t)(b * SEQ + t) * CH)
                                 : (sc + (size_t)(t - SEQ) * CH);
    float4 v = *(const float4*)(src + c4);
    *(float4*)(g_XT + (size_t)row * CH + c4) =
        make_float4(tf32r(v.x), tf32r(v.y), tf32r(v.z), tf32r(v.w));
}

// =====================================================================
// Prep B: tf32-round weights (dst selected inside device code)
// =====================================================================
template<int WHICH>
__global__ __launch_bounds__(256) void w_round(const float* __restrict__ src, int n4)
{
    int i = blockIdx.x * 256 + threadIdx.x;
    if (i >= n4) return;
    float* dst = WHICH ? g_W2 : g_W1;
    float4 v = *(const float4*)(src + (size_t)i * 4);
    *(float4*)(dst + (size_t)i * 4) =
        make_float4(tf32r(v.x), tf32r(v.y), tf32r(v.z), tf32r(v.w));
}

// =====================================================================
// GEMM v4: as v3 (3-stage cp.async, 1 sync/k-tile) + explicit ks-level
// fragment double-buffering to break the LDS->HMMA serial chain.
// MODE 0: A=g_XT,B=g_W1 -> scatter g_Q/g_K/g_V.  MODE 1: A=g_AT,B=g_W2 -> out.
// =====================================================================
#define AW 36
#define BW 136
#define STGW (128*AW + 32*BW)    // 8960 words
#define NSTG 3
#define GSM (NSTG*STGW*4)        // 107520 B

template<int MODE>
__global__ __launch_bounds__(128, 2)
void gemm4(float* __restrict__ out, const float* __restrict__ bias)
{
    constexpr int NKT = CH / 32;   // 24
    extern __shared__ unsigned sm[];

    const float* A   = (MODE == 0) ? g_XT : g_AT;
    const float* B   = (MODE == 0) ? g_W1 : g_W2;
    const int    ldb = (MODE == 0) ? QKVN : CH;

    const int tid = threadIdx.x, wid = tid >> 5, lane = tid & 31;
    const int g = lane >> 2, tg = lane & 3;
    const int mt = blockIdx.y, nt = blockIdx.x;
    const int wm = (wid & 1) * 64, wn = (wid >> 1) * 64;

    const int row_a = tid >> 3, kc_a = (tid & 7) * 4;
    const int row_b = tid >> 5, nc_b = (tid & 31) * 4;
    const uint32_t sb = smem_u32(sm);

    auto issue = [&](int kt){
        const int s = kt % NSTG;
        const int kt0 = kt * 32;
        uint32_t ab = sb + (uint32_t)(s * STGW) * 4u;
        uint32_t bb = ab + 128u * AW * 4u;
        #pragma unroll
        for (int i = 0; i < 8; i++) {
            int r = row_a + i * 16;
            cpa16(ab + (uint32_t)(r * AW + kc_a) * 4u,
                  A + (size_t)(mt * 128 + r) * CH + kt0 + kc_a);
        }
        #pragma unroll
        for (int i = 0; i < 8; i++) {
            int r = row_b + i * 4;
            cpa16(bb + (uint32_t)(r * BW + nc_b) * 4u,
                  B + (size_t)(kt0 + r) * ldb + nt * 128 + nc_b);
        }
        cp_commit();
    };

    float C[4][8][4];
    #pragma unroll
    for (int i = 0; i < 4; i++)
        #pragma unroll
        for (int j = 0; j < 8; j++)
            #pragma unroll
            for (int e = 0; e < 4; e++) C[i][j][e] = 0.f;

    issue(0);
    issue(1);

    for (int kt = 0; kt < NKT; kt++) {
        cp_wait1();
        __syncthreads();
        if (kt + 2 < NKT) issue(kt + 2);
        else cp_commit();

        const unsigned* As = sm + (kt % NSTG) * STGW;
        const unsigned* Bs = As + 128 * AW;

        // ---- ks-level fragment double-buffer ----
        unsigned af[2][4][4], bf[2][8][2];
        auto ldfrag = [&](int ks, int p){
            const int kk = ks * 8;
            #pragma unroll
            for (int mf = 0; mf < 4; mf++) {
                int r0 = wm + mf * 16 + g;
                af[p][mf][0] = As[(r0    ) * AW + kk + tg];
                af[p][mf][1] = As[(r0 + 8) * AW + kk + tg];
                af[p][mf][2] = As[(r0    ) * AW + kk + tg + 4];
                af[p][mf][3] = As[(r0 + 8) * AW + kk + tg + 4];
            }
            #pragma unroll
            for (int nf = 0; nf < 8; nf++) {
                int c0 = wn + nf * 8 + g;
                bf[p][nf][0] = Bs[(kk + tg    ) * BW + c0];
                bf[p][nf][1] = Bs[(kk + tg + 4) * BW + c0];
            }
        };
        ldfrag(0, 0);
        #pragma unroll
        for (int ks = 0; ks < 4; ks++) {
            if (ks < 3) ldfrag(ks + 1, (ks + 1) & 1);
            const int p = ks & 1;
            #pragma unroll
            for (int mf = 0; mf < 4; mf++)
                #pragma unroll
                for (int nf = 0; nf < 8; nf++)
                    mma8(C[mf][nf], af[p][mf], bf[p][nf]);
        }
    }

    // ---- epilogue ----
    #pragma unroll
    for (int mf = 0; mf < 4; mf++) {
        #pragma unroll
        for (int nf = 0; nf < 8; nf++) {
            #pragma unroll
            for (int e = 0; e < 4; e++) {
                int r = mt * 128 + wm + mf * 16 + g + ((e >= 2) ? 8 : 0);
                int c = nt * 128 + wn + nf * 8 + tg * 2 + (e & 1);
                float v = C[mf][nf][e];
                if (MODE == 1) {
                    out[(size_t)r * CH + c] = v + bias[c];
                } else {
                    if (r >= MQKV) continue;
                    int b = r / NTOK, t = r - b * NTOK;
                    int wc = c / CH, cc = c - wc * CH;
                    int h = cc >> 6, d = cc & 63;
                    float vr = tf32r(v);
                    if (wc == 0) {
                        if (t < SEQ)
                            g_Q[((size_t)(b * HEADS + h) * SEQ + t) * DHEAD + d] = vr;
                    } else if (wc == 1) {
                        g_K[((size_t)(b * HEADS + h) * NKV + t) * DHEAD + d] = vr;
                    } else {
                        g_V[((size_t)(b * HEADS + h) * NKV + t) * DHEAD + d] = vr;
                    }
                }
            }
        }
    }
}

// =====================================================================
// Attention v4: round-10 dataflow + 2-stage cp.async double-buffer for
// K/V (dynamic smem: K[2][64][76], V[2][64][72] = 75776 B, 3 CTAs/SM).
// Tile kt+1 issued right after the top barrier of iter kt -> staging
// latency hidden. P reuses the CURRENT K buffer (not the one in flight).
// =====================================================================
#define KW 76
#define VW 72
#define KBUF_W (64*KW)           // 4864 words
#define VBUF_W (64*VW)           // 4608 words
#define ATT_SMEM ((2*KBUF_W + 2*VBUF_W)*4)   // 75776 B

__global__ __launch_bounds__(128) void attn_k()
{
    extern __shared__ unsigned smema[];
    const int bh = blockIdx.y, qt = blockIdx.x;
    const int b = bh / HEADS, h = bh - b * HEADS;
    const int tid = threadIdx.x;
    const int w = tid >> 5, lane = tid & 31;
    const int g = lane >> 2, tg = lane & 3;

    const unsigned* Qu = (const unsigned*)g_Q + (size_t)bh * SEQ * DHEAD;
    const float* Kp = g_K + (size_t)bh * NKV * DHEAD;
    const float* Vp = g_V + (size_t)bh * NKV * DHEAD;
    const uint32_t sb = smem_u32(smema);
    const int q0 = qt * 64 + w * 16;

    // staging: 8 K-chunks + 8 V-chunks of 16B per thread per tile
    const int srow = tid >> 4, sc4 = (tid & 15) * 4;   // +i*8 rows
    auto issue = [&](int kt){
        const int s = kt & 1;
        const int j0 = kt * 64;
        uint32_t kb = sb + (uint32_t)(s * KBUF_W) * 4u;
        uint32_t vb = sb + (uint32_t)(2 * KBUF_W + s * VBUF_W) * 4u;
        #pragma unroll
        for (int i = 0; i < 8; i++) {
            int row = srow + i * 8;
            cpa16(kb + (uint32_t)(row * KW + sc4) * 4u,
                  Kp + (size_t)(j0 + row) * DHEAD + sc4);
        }
        #pragma unroll
        for (int i = 0; i < 8; i++) {
            int row = srow + i * 8;
            cpa16(vb + (uint32_t)(row * VW + sc4) * 4u,
                  Vp + (size_t)(j0 + row) * DHEAD + sc4);
        }
        cp_commit();
    };

    // Q fragments (pre-rounded tf32 bits)
    unsigned aq[8][4];
    #pragma unroll
    for (int ks = 0; ks < 8; ks++) {
        aq[ks][0] = Qu[(size_t)(q0 + g    ) * DHEAD + ks * 8 + tg    ];
        aq[ks][1] = Qu[(size_t)(q0 + g + 8) * DHEAD + ks * 8 + tg    ];
        aq[ks][2] = Qu[(size_t)(q0 + g    ) * DHEAD + ks * 8 + tg + 4];
        aq[ks][3] = Qu[(size_t)(q0 + g + 8) * DHEAD + ks * 8 + tg + 4];
    }

    float O[8][4];
    #pragma unroll
    for (int i = 0; i < 8; i++)
        #pragma unroll
        for (int e = 0; e < 4; e++) O[i][e] = 0.f;
    float mrow[2] = { -1e30f, -1e30f };
    float lrow[2] = { 0.f, 0.f };

    issue(0);

    for (int kt = 0; kt < NKV / 64; kt++) {
        const int s = kt & 1;
        const int j0 = kt * 64;
        unsigned* Ks = smema + s * KBUF_W;                 // [64][KW]; becomes P
        unsigned* Vs = smema + 2 * KBUF_W + s * VBUF_W;    // [64][VW]

        cp_wait0();          // tile kt landed (only group in flight)
        __syncthreads();     // visibility; also closes ALL reads of tile kt-1
        if (kt + 1 < NKV / 64) issue(kt + 1);   // into the other buffer — safe

        // ---- S = Q @ K^T ----
        float S[8][4];
        #pragma unroll
        for (int i = 0; i < 8; i++)
            #pragma unroll
            for (int e = 0; e < 4; e++) S[i][e] = 0.f;
        #pragma unroll
        for (int nf = 0; nf < 8; nf++) {
            #pragma unroll
            for (int ks = 0; ks < 8; ks++) {
                unsigned bb[2];
                bb[0] = Ks[(nf * 8 + g) * KW + ks * 8 + tg    ];
                bb[1] = Ks[(nf * 8 + g) * KW + ks * 8 + tg + 4];
                mma8(S[nf], aq[ks], bb);
            }
        }
        __syncthreads();     // all S reads of Ks done before it becomes P

        // ---- scale + mask ----
        #pragma unroll
        for (int nf = 0; nf < 8; nf++) {
            #pragma unroll
            for (int e = 0; e < 4; e++) {
                float sv = S[nf][e] * 0.125f;
                int j = j0 + nf * 8 + tg * 2 + (e & 1);
                if (j >= NTOK) sv = -1e30f;
                S[nf][e] = sv;
            }
        }
        // ---- online softmax ----
        #pragma unroll
        for (int r = 0; r < 2; r++) {
            float mx = -1e30f;
            #pragma unroll
            for (int nf = 0; nf < 8; nf++) {
                mx = fmaxf(mx, S[nf][2 * r]);
                mx = fmaxf(mx, S[nf][2 * r + 1]);
            }
            mx = fmaxf(mx, __shfl_xor_sync(0xffffffffu, mx, 1));
            mx = fmaxf(mx, __shfl_xor_sync(0xffffffffu, mx, 2));
            float mnew = fmaxf(mrow[r], mx);
            float alpha = __expf(mrow[r] - mnew);
            float sum = 0.f;
            #pragma unroll
            for (int nf = 0; nf < 8; nf++) {
                float p0 = __expf(S[nf][2 * r    ] - mnew);
                float p1 = __expf(S[nf][2 * r + 1] - mnew);
                S[nf][2 * r] = p0; S[nf][2 * r + 1] = p1;
                sum += p0 + p1;
            }
            sum += __shfl_xor_sync(0xffffffffu, sum, 1);
            sum += __shfl_xor_sync(0xffffffffu, sum, 2);
            lrow[r] = lrow[r] * alpha + sum;
            mrow[r] = mnew;
            #pragma unroll
            for (int nf = 0; nf < 8; nf++) {
                O[nf][2 * r] *= alpha; O[nf][2 * r + 1] *= alpha;
            }
        }
        // ---- store P into Ks (warp-private 16 rows) ----
        #pragma unroll
        for (int nf = 0; nf < 8; nf++) {
            Ks[(w * 16 + g    ) * KW + nf * 8 + tg * 2    ] = f2t(S[nf][0]);
            Ks[(w * 16 + g    ) * KW + nf * 8 + tg * 2 + 1] = f2t(S[nf][1]);
            Ks[(w * 16 + g + 8) * KW + nf * 8 + tg * 2    ] = f2t(S[nf][2]);
            Ks[(w * 16 + g + 8) * KW + nf * 8 + tg * 2 + 1] = f2t(S[nf][3]);
        }
        __syncwarp();
        // ---- O += P @ V ----
        #pragma unroll
        for (int ks = 0; ks < 8; ks++) {
            unsigned ap[4];
            ap[0] = Ks[(w * 16 + g    ) * KW + ks * 8 + tg    ];
            ap[1] = Ks[(w * 16 + g + 8) * KW + ks * 8 + tg    ];
            ap[2] = Ks[(w * 16 + g    ) * KW + ks * 8 + tg + 4];
            ap[3] = Ks[(w * 16 + g + 8) * KW + ks * 8 + tg + 4];
            #pragma unroll
            for (int nf = 0; nf < 8; nf++) {
                unsigned bb[2];
                bb[0] = Vs[(ks * 8 + tg    ) * VW + nf * 8 + g];
                bb[1] = Vs[(ks * 8 + tg + 4) * VW + nf * 8 + g];
                mma8(O[nf], ap, bb);
            }
        }
        // no end barrier: next iteration's top barrier closes these reads
    }
    // ---- normalize, tf32-round, write g_AT ----
    float inv0 = 1.f / lrow[0], inv1 = 1.f / lrow[1];
    int row0 = b * SEQ + qt * 64 + w * 16 + g;
    #pragma unroll
    for (int nf = 0; nf < 8; nf++) {
        int col = h * DHEAD + nf * 8 + tg * 2;
        g_AT[(size_t)row0 * CH + col    ] = tf32r(O[nf][0] * inv0);
        g_AT[(size_t)row0 * CH + col + 1] = tf32r(O[nf][1] * inv0);
        g_AT[(size_t)(row0 + 8) * CH + col    ] = tf32r(O[nf][2] * inv1);
        g_AT[(size_t)(row0 + 8) * CH + col + 1] = tf32r(O[nf][3] * inv1);
    }
}

// =====================================================================
extern "C" void kernel_launch(void* const* d_in, const int* in_sizes, int n_in,
                              void* d_out, int out_size)
{
    const float* x     = (const float*)d_in[0];
    const float* sc    = (const float*)d_in[1];
    const float* Wqkv  = (const float*)d_in[2];
    const float* Wproj = (const float*)d_in[3];
    const float* bproj = (const float*)d_in[4];
    float* out = (float*)d_out;

    cudaFuncSetAttribute(gemm4<0>, cudaFuncAttributeMaxDynamicSharedMemorySize, GSM);
    cudaFuncSetAttribute(gemm4<1>, cudaFuncAttributeMaxDynamicSharedMemorySize, GSM);
    cudaFuncSetAttribute(attn_k,   cudaFuncAttributeMaxDynamicSharedMemorySize, ATT_SMEM);

    {
        size_t tot = (size_t)MQKV * (CH / 4);
        xt_copy<<<(unsigned)((tot + 255) / 256), 256>>>(x, sc);
    }
    w_round<0><<<(CH * QKVN / 4 + 255) / 256, 256>>>(Wqkv, CH * QKVN / 4);
    w_round<1><<<(CH * CH / 4 + 255) / 256, 256>>>(Wproj, CH * CH / 4);

    // qkv: M=19584 (153 m-tiles), N=2304 (18 n-tiles)
    gemm4<0><<<dim3(18, 153), 128, GSM>>>(nullptr, nullptr);
    // attention: 16 q-tiles x 192 (b,h)
    attn_k<<<dim3(16, 192), 128, ATT_SMEM>>>();
    // proj: M=16384 (128 m-tiles), N=768 (6 n-tiles)
    gemm4<1><<<dim3(6, 128), 128, GSM>>>(out, bproj);
}

// round 12
// speedup vs baseline: 32.0744x; 1.0463x over previous
#include <cuda_runtime.h>
#include <cstdint>

#define BATCH 16
#define SEQ   1024
#define CH    768
#define HEADS 12
#define DHEAD 64
#define NTOK  1220              // 1024 + 196
#define NKV   1280              // padded key count
#define MQKV  (BATCH*NTOK)      // 19520 rows of xt
#define MPAD  19584             // 153*128
#define QKVN  (3*CH)            // 2304

// ---------------- scratch (zero-initialized). RULE: referenced ONLY in
// device code, never passed as kernel arguments. ----------------------------
__device__ float g_XT[MPAD*CH];                  // xt, tf32-rounded; pad rows 0
__device__ float g_W1[CH*QKVN];                  // W_qkv, tf32-rounded
__device__ float g_W2[CH*CH];                    // W_proj, tf32-rounded
__device__ float g_Q [BATCH*HEADS*SEQ *DHEAD];   // tf32-rounded
__device__ float g_K [BATCH*HEADS*NKV *DHEAD];   // tf32-rounded; pad rows 0
__device__ float g_V [BATCH*HEADS*NKV *DHEAD];   // tf32-rounded
__device__ float g_AT[BATCH*SEQ*CH];             // attn out, tf32-rounded

// ---------------- helpers ----------------
__device__ __forceinline__ unsigned f2t(float x){
    unsigned u; asm("cvt.rna.tf32.f32 %0, %1;" : "=r"(u) : "f"(x)); return u;
}
__device__ __forceinline__ float tf32r(float x){
    unsigned u; asm("cvt.rna.tf32.f32 %0, %1;" : "=r"(u) : "f"(x));
    return __uint_as_float(u);
}
__device__ __forceinline__ void mma8(float* c, const unsigned* a, const unsigned* b){
    asm volatile("mma.sync.aligned.m16n8k8.row.col.f32.tf32.tf32.f32 "
        "{%0,%1,%2,%3}, {%4,%5,%6,%7}, {%8,%9}, {%0,%1,%2,%3};"
        : "+f"(c[0]), "+f"(c[1]), "+f"(c[2]), "+f"(c[3])
        : "r"(a[0]), "r"(a[1]), "r"(a[2]), "r"(a[3]), "r"(b[0]), "r"(b[1]));
}
__device__ __forceinline__ uint32_t smem_u32(const void* p){
    uint32_t a;
    asm("{ .reg .u64 t; cvta.to.shared.u64 t, %1; cvt.u32.u64 %0, t; }" : "=r"(a) : "l"(p));
    return a;
}
__device__ __forceinline__ void cpa16(uint32_t dst, const float* src){
    asm volatile("cp.async.cg.shared.global [%0], [%1], 16;" :: "r"(dst), "l"(src) : "memory");
}
__device__ __forceinline__ void cp_commit(){
    asm volatile("cp.async.commit_group;" ::: "memory");
}
__device__ __forceinline__ void cp_wait0(){
    asm volatile("cp.async.wait_group 0;" ::: "memory");
}

// =====================================================================
// Prep A: materialize xt rows, tf32-rounded
// =====================================================================
__global__ __launch_bounds__(256) void xt_copy(
    const float* __restrict__ x, const float* __restrict__ sc)
{
    size_t i = (size_t)blockIdx.x * blockDim.x + threadIdx.x;
    size_t tot = (size_t)MQKV * (CH/4);
    if (i >= tot) return;
    int row = (int)(i / (CH/4));
    int c4  = (int)(i % (CH/4)) * 4;
    int b = row / NTOK, t = row - b * NTOK;
    const float* src = (t < SEQ) ? (x + (size_t)(b * SEQ + t) * CH)
                                 : (sc + (size_t)(t - SEQ) * CH);
    float4 v = *(const float4*)(src + c4);
    *(float4*)(g_XT + (size_t)row * CH + c4) =
        make_float4(tf32r(v.x), tf32r(v.y), tf32r(v.z), tf32r(v.w));
}

// =====================================================================
// Prep B: tf32-round weights (dst selected inside device code)
// =====================================================================
template<int WHICH>
__global__ __launch_bounds__(256) void w_round(const float* __restrict__ src, int n4)
{
    int i = blockIdx.x * 256 + threadIdx.x;
    if (i >= n4) return;
    float* dst = WHICH ? g_W2 : g_W1;
    float4 v = *(const float4*)(src + (size_t)i * 4);
    *(float4*)(dst + (size_t)i * 4) =
        make_float4(tf32r(v.x), tf32r(v.y), tf32r(v.z), tf32r(v.w));
}

// =====================================================================
// GEMM v5: 128x128 block tile, 4 warps of 64x64, k-tile 32.
// 2-stage cp.async pipeline, one sync per k-tile, __launch_bounds__(128,3)
// -> 3 CTAs/SM (12 warps). ptxas register-capped at 170 (accept mild spill).
// MODE 0: A=g_XT,B=g_W1 -> scatter g_Q/g_K/g_V.  MODE 1: A=g_AT,B=g_W2 -> out.
// =====================================================================
#define AW 36
#define BW 136
#define STGW (128*AW + 32*BW)    // 8960 words
#define NSTG 2
#define GSM (NSTG*STGW*4)        // 71680 B

template<int MODE>
__global__ __launch_bounds__(128, 3)
void gemm5(float* __restrict__ out, const float* __restrict__ bias)
{
    constexpr int NKT = CH / 32;   // 24
    extern __shared__ unsigned sm[];

    const float* A   = (MODE == 0) ? g_XT : g_AT;
    const float* B   = (MODE == 0) ? g_W1 : g_W2;
    const int    ldb = (MODE == 0) ? QKVN : CH;

    const int tid = threadIdx.x, wid = tid >> 5, lane = tid & 31;
    const int g = lane >> 2, tg = lane & 3;
    const int mt = blockIdx.y, nt = blockIdx.x;
    const int wm = (wid & 1) * 64, wn = (wid >> 1) * 64;

    const int row_a = tid >> 3, kc_a = (tid & 7) * 4;
    const int row_b = tid >> 5, nc_b = (tid & 31) * 4;
    const uint32_t sb = smem_u32(sm);

    auto issue = [&](int kt){
        const int s = kt & 1;
        const int kt0 = kt * 32;
        uint32_t ab = sb + (uint32_t)(s * STGW) * 4u;
        uint32_t bb = ab + 128u * AW * 4u;
        #pragma unroll
        for (int i = 0; i < 8; i++) {
            int r = row_a + i * 16;
            cpa16(ab + (uint32_t)(r * AW + kc_a) * 4u,
                  A + (size_t)(mt * 128 + r) * CH + kt0 + kc_a);
        }
        #pragma unroll
        for (int i = 0; i < 8; i++) {
            int r = row_b + i * 4;
            cpa16(bb + (uint32_t)(r * BW + nc_b) * 4u,
                  B + (size_t)(kt0 + r) * ldb + nt * 128 + nc_b);
        }
        cp_commit();
    };

    float C[4][8][4];
    #pragma unroll
    for (int i = 0; i < 4; i++)
        #pragma unroll
        for (int j = 0; j < 8; j++)
            #pragma unroll
            for (int e = 0; e < 4; e++) C[i][j][e] = 0.f;

    issue(0);

    for (int kt = 0; kt < NKT; kt++) {
        cp_wait0();          // tile kt landed (only group in flight)
        __syncthreads();     // visibility; closes reads of the other buffer
        if (kt + 1 < NKT) issue(kt + 1);   // lands during compute of kt

        const unsigned* As = sm + (kt & 1) * STGW;
        const unsigned* Bs = As + 128 * AW;
        #pragma unroll
        for (int ks = 0; ks < 4; ks++) {
            const int kk = ks * 8;
            unsigned a[4][4];
            #pragma unroll
            for (int mf = 0; mf < 4; mf++) {
                int r0 = wm + mf * 16 + g;
                a[mf][0] = As[(r0    ) * AW + kk + tg];
                a[mf][1] = As[(r0 + 8) * AW + kk + tg];
                a[mf][2] = As[(r0    ) * AW + kk + tg + 4];
                a[mf][3] = As[(r0 + 8) * AW + kk + tg + 4];
            }
            unsigned bf[8][2];
            #pragma unroll
            for (int nf = 0; nf < 8; nf++) {
                int c0 = wn + nf * 8 + g;
                bf[nf][0] = Bs[(kk + tg    ) * BW + c0];
                bf[nf][1] = Bs[(kk + tg + 4) * BW + c0];
            }
            #pragma unroll
            for (int mf = 0; mf < 4; mf++)
                #pragma unroll
                for (int nf = 0; nf < 8; nf++)
                    mma8(C[mf][nf], a[mf], bf[nf]);
        }
    }

    // ---- epilogue ----
    #pragma unroll
    for (int mf = 0; mf < 4; mf++) {
        #pragma unroll
        for (int nf = 0; nf < 8; nf++) {
            #pragma unroll
            for (int e = 0; e < 4; e++) {
                int r = mt * 128 + wm + mf * 16 + g + ((e >= 2) ? 8 : 0);
                int c = nt * 128 + wn + nf * 8 + tg * 2 + (e & 1);
                float v = C[mf][nf][e];
                if (MODE == 1) {
                    out[(size_t)r * CH + c] = v + bias[c];
                } else {
                    if (r >= MQKV) continue;
                    int b = r / NTOK, t = r - b * NTOK;
                    int wc = c / CH, cc = c - wc * CH;
                    int h = cc >> 6, d = cc & 63;
                    float vr = tf32r(v);
                    if (wc == 0) {
                        if (t < SEQ)
                            g_Q[((size_t)(b * HEADS + h) * SEQ + t) * DHEAD + d] = vr;
                    } else if (wc == 1) {
                        g_K[((size_t)(b * HEADS + h) * NKV + t) * DHEAD + d] = vr;
                    } else {
                        g_V[((size_t)(b * HEADS + h) * NKV + t) * DHEAD + d] = vr;
                    }
                }
            }
        }
    }
}

// =====================================================================
// Attention v4 (unchanged from round 11 — proven): 2-stage cp.async
// double-buffered K/V, conflict-free strides, raw-bit Q fragments.
// =====================================================================
#define KW 76
#define VW 72
#define KBUF_W (64*KW)           // 4864 words
#define VBUF_W (64*VW)           // 4608 words
#define ATT_SMEM ((2*KBUF_W + 2*VBUF_W)*4)   // 75776 B

__global__ __launch_bounds__(128) void attn_k()
{
    extern __shared__ unsigned smema[];
    const int bh = blockIdx.y, qt = blockIdx.x;
    const int b = bh / HEADS, h = bh - b * HEADS;
    const int tid = threadIdx.x;
    const int w = tid >> 5, lane = tid & 31;
    const int g = lane >> 2, tg = lane & 3;

    const unsigned* Qu = (const unsigned*)g_Q + (size_t)bh * SEQ * DHEAD;
    const float* Kp = g_K + (size_t)bh * NKV * DHEAD;
    const float* Vp = g_V + (size_t)bh * NKV * DHEAD;
    const uint32_t sb = smem_u32(smema);
    const int q0 = qt * 64 + w * 16;

    const int srow = tid >> 4, sc4 = (tid & 15) * 4;
    auto issue = [&](int kt){
        const int s = kt & 1;
        const int j0 = kt * 64;
        uint32_t kb = sb + (uint32_t)(s * KBUF_W) * 4u;
        uint32_t vb = sb + (uint32_t)(2 * KBUF_W + s * VBUF_W) * 4u;
        #pragma unroll
        for (int i = 0; i < 8; i++) {
            int row = srow + i * 8;
            cpa16(kb + (uint32_t)(row * KW + sc4) * 4u,
                  Kp + (size_t)(j0 + row) * DHEAD + sc4);
        }
        #pragma unroll
        for (int i = 0; i < 8; i++) {
            int row = srow + i * 8;
            cpa16(vb + (uint32_t)(row * VW + sc4) * 4u,
                  Vp + (size_t)(j0 + row) * DHEAD + sc4);
        }
        cp_commit();
    };

    unsigned aq[8][4];
    #pragma unroll
    for (int ks = 0; ks < 8; ks++) {
        aq[ks][0] = Qu[(size_t)(q0 + g    ) * DHEAD + ks * 8 + tg    ];
        aq[ks][1] = Qu[(size_t)(q0 + g + 8) * DHEAD + ks * 8 + tg    ];
        aq[ks][2] = Qu[(size_t)(q0 + g    ) * DHEAD + ks * 8 + tg + 4];
        aq[ks][3] = Qu[(size_t)(q0 + g + 8) * DHEAD + ks * 8 + tg + 4];
    }

    float O[8][4];
    #pragma unroll
    for (int i = 0; i < 8; i++)
        #pragma unroll
        for (int e = 0; e < 4; e++) O[i][e] = 0.f;
    float mrow[2] = { -1e30f, -1e30f };
    float lrow[2] = { 0.f, 0.f };

    issue(0);

    for (int kt = 0; kt < NKV / 64; kt++) {
        const int s = kt & 1;
        const int j0 = kt * 64;
        unsigned* Ks = smema + s * KBUF_W;
        unsigned* Vs = smema + 2 * KBUF_W + s * VBUF_W;

        cp_wait0();
        __syncthreads();
        if (kt + 1 < NKV / 64) issue(kt + 1);

        float S[8][4];
        #pragma unroll
        for (int i = 0; i < 8; i++)
            #pragma unroll
            for (int e = 0; e < 4; e++) S[i][e] = 0.f;
        #pragma unroll
        for (int nf = 0; nf < 8; nf++) {
            #pragma unroll
            for (int ks = 0; ks < 8; ks++) {
                unsigned bb[2];
                bb[0] = Ks[(nf * 8 + g) * KW + ks * 8 + tg    ];
                bb[1] = Ks[(nf * 8 + g) * KW + ks * 8 + tg + 4];
                mma8(S[nf], aq[ks], bb);
            }
        }
        __syncthreads();

        #pragma unroll
        for (int nf = 0; nf < 8; nf++) {
            #pragma unroll
            for (int e = 0; e < 4; e++) {
                float sv = S[nf][e] * 0.125f;
                int j = j0 + nf * 8 + tg * 2 + (e & 1);
                if (j >= NTOK) sv = -1e30f;
                S[nf][e] = sv;
            }
        }
        #pragma unroll
        for (int r = 0; r < 2; r++) {
            float mx = -1e30f;
            #pragma unroll
            for (int nf = 0; nf < 8; nf++) {
                mx = fmaxf(mx, S[nf][2 * r]);
                mx = fmaxf(mx, S[nf][2 * r + 1]);
            }
            mx = fmaxf(mx, __shfl_xor_sync(0xffffffffu, mx, 1));
            mx = fmaxf(mx, __shfl_xor_sync(0xffffffffu, mx, 2));
            float mnew = fmaxf(mrow[r], mx);
            float alpha = __expf(mrow[r] - mnew);
            float sum = 0.f;
            #pragma unroll
            for (int nf = 0; nf < 8; nf++) {
                float p0 = __expf(S[nf][2 * r    ] - mnew);
                float p1 = __expf(S[nf][2 * r + 1] - mnew);
                S[nf][2 * r] = p0; S[nf][2 * r + 1] = p1;
                sum += p0 + p1;
            }
            sum += __shfl_xor_sync(0xffffffffu, sum, 1);
            sum += __shfl_xor_sync(0xffffffffu, sum, 2);
            lrow[r] = lrow[r] * alpha + sum;
            mrow[r] = mnew;
            #pragma unroll
            for (int nf = 0; nf < 8; nf++) {
                O[nf][2 * r] *= alpha; O[nf][2 * r + 1] *= alpha;
            }
        }
        #pragma unroll
        for (int nf = 0; nf < 8; nf++) {
            Ks[(w * 16 + g    ) * KW + nf * 8 + tg * 2    ] = f2t(S[nf][0]);
            Ks[(w * 16 + g    ) * KW + nf * 8 + tg * 2 + 1] = f2t(S[nf][1]);
            Ks[(w * 16 + g + 8) * KW + nf * 8 + tg * 2    ] = f2t(S[nf][2]);
            Ks[(w * 16 + g + 8) * KW + nf * 8 + tg * 2 + 1] = f2t(S[nf][3]);
        }
        __syncwarp();
        #pragma unroll
        for (int ks = 0; ks < 8; ks++) {
            unsigned ap[4];
            ap[0] = Ks[(w * 16 + g    ) * KW + ks * 8 + tg    ];
            ap[1] = Ks[(w * 16 + g + 8) * KW + ks * 8 + tg    ];
            ap[2] = Ks[(w * 16 + g    ) * KW + ks * 8 + tg + 4];
            ap[3] = Ks[(w * 16 + g + 8) * KW + ks * 8 + tg + 4];
            #pragma unroll
            for (int nf = 0; nf < 8; nf++) {
                unsigned bb[2];
                bb[0] = Vs[(ks * 8 + tg    ) * VW + nf * 8 + g];
                bb[1] = Vs[(ks * 8 + tg + 4) * VW + nf * 8 + g];
                mma8(O[nf], ap, bb);
            }
        }
    }
    float inv0 = 1.f / lrow[0], inv1 = 1.f / lrow[1];
    int row0 = b * SEQ + qt * 64 + w * 16 + g;
    #pragma unroll
    for (int nf = 0; nf < 8; nf++) {
        int col = h * DHEAD + nf * 8 + tg * 2;
        g_AT[(size_t)row0 * CH + col    ] = tf32r(O[nf][0] * inv0);
        g_AT[(size_t)row0 * CH + col + 1] = tf32r(O[nf][1] * inv0);
        g_AT[(size_t)(row0 + 8) * CH + col    ] = tf32r(O[nf][2] * inv1);
        g_AT[(size_t)(row0 + 8) * CH + col + 1] = tf32r(O[nf][3] * inv1);
    }
}

// =====================================================================
extern "C" void kernel_launch(void* const* d_in, const int* in_sizes, int n_in,
                              void* d_out, int out_size)
{
    const float* x     = (const float*)d_in[0];
    const float* sc    = (const float*)d_in[1];
    const float* Wqkv  = (const float*)d_in[2];
    const float* Wproj = (const float*)d_in[3];
    const float* bproj = (const float*)d_in[4];
    float* out = (float*)d_out;

    cudaFuncSetAttribute(gemm5<0>, cudaFuncAttributeMaxDynamicSharedMemorySize, GSM);
    cudaFuncSetAttribute(gemm5<1>, cudaFuncAttributeMaxDynamicSharedMemorySize, GSM);
    cudaFuncSetAttribute(attn_k,   cudaFuncAttributeMaxDynamicSharedMemorySize, ATT_SMEM);

    {
        size_t tot = (size_t)MQKV * (CH / 4);
        xt_copy<<<(unsigned)((tot + 255) / 256), 256>>>(x, sc);
    }
    w_round<0><<<(CH * QKVN / 4 + 255) / 256, 256>>>(Wqkv, CH * QKVN / 4);
    w_round<1><<<(CH * CH / 4 + 255) / 256, 256>>>(Wproj, CH * CH / 4);

    // qkv: M=19584 (153 m-tiles), N=2304 (18 n-tiles)
    gemm5<0><<<dim3(18, 153), 128, GSM>>>(nullptr, nullptr);
    // attention: 16 q-tiles x 192 (b,h)
    attn_k<<<dim3(16, 192), 128, ATT_SMEM>>>();
    // proj: M=16384 (128 m-tiles), N=768 (6 n-tiles)
    gemm5<1><<<dim3(6, 128), 128, GSM>>>(out, bproj);
}